// round 8
// baseline (speedup 1.0000x reference)
#include <cuda_runtime.h>
#include <cuda_bf16.h>
#include <cstdint>

#define NN 100000
#define NE 800000
#define F  128
#define NT 782              // ceil(NN/128) node tiles
#define NB 391              // ceil(NN/256) scan blocks
#define LDA 136             // smem row stride in bf16 elements
#define REG_BYTES (128 * LDA * 2)   // 34816

// fused kernel smem layout (bytes)
#define AS_OFF 0
#define AH_OFF 65536
#define AL_OFF (AH_OFF + REG_BYTES)
#define BH_OFF (AL_OFF + REG_BYTES)
#define BL_OFF (BH_OFF + REG_BYTES)
#define SMEM_FUSED (BL_OFF + REG_BYTES)   // 204800

// ---------------- scratch ----------------------------------------------------
__device__ int      g_indeg_i [NN];
__device__ int      g_outdeg_i[NN];
__device__ int      g_rowstart[NN];
__device__ int      g_cursor  [NN];
__device__ float    g_rin     [NN];
__device__ int      g_blksum  [512];
__device__ unsigned g_csr     [NE];
__device__ float    g_hsum [(size_t)NN * F];
__device__ float    g_hprod[(size_t)NN * F];
__device__ __nv_bfloat16 g_w1h[F * F], g_w1l[F * F];
__device__ __nv_bfloat16 g_w2h[F * F], g_w2l[F * F];
__device__ __nv_bfloat16 g_vh [F * F], g_vl [F * F];

// ---------------- helpers ----------------------------------------------------
__device__ __forceinline__ uint32_t smem_to_u32(const void* p) {
    uint32_t a;
    asm("{ .reg .u64 t; cvta.to.shared.u64 t, %1; cvt.u32.u64 %0, t; }" : "=r"(a) : "l"(p));
    return a;
}

__device__ __forceinline__ void ldsm4(uint32_t& r0, uint32_t& r1, uint32_t& r2, uint32_t& r3,
                                      uint32_t addr) {
    asm volatile("ldmatrix.sync.aligned.m8n8.x4.shared.b16 {%0,%1,%2,%3}, [%4];"
                 : "=r"(r0), "=r"(r1), "=r"(r2), "=r"(r3) : "r"(addr));
}

__device__ __forceinline__ void mma_bf16(float* c, const uint32_t* a, const uint32_t* b) {
    asm volatile("mma.sync.aligned.m16n8k16.row.col.f32.bf16.bf16.f32 "
                 "{%0,%1,%2,%3}, {%4,%5,%6,%7}, {%8,%9}, {%0,%1,%2,%3};"
                 : "+f"(c[0]), "+f"(c[1]), "+f"(c[2]), "+f"(c[3])
                 : "r"(a[0]), "r"(a[1]), "r"(a[2]), "r"(a[3]), "r"(b[0]), "r"(b[1]));
}

__device__ __forceinline__ void split4(float4 x, uint2& H, uint2& L) {
    float xs[4] = {x.x, x.y, x.z, x.w};
    unsigned short h[4], l[4];
#pragma unroll
    for (int j = 0; j < 4; j++) {
        __nv_bfloat16 bh = __float2bfloat16(xs[j]);
        float r = xs[j] - __bfloat162float(bh);
        __nv_bfloat16 bl = __float2bfloat16(r);
        h[j] = __bfloat16_as_ushort(bh);
        l[j] = __bfloat16_as_ushort(bl);
    }
    H = make_uint2((uint32_t)h[0] | ((uint32_t)h[1] << 16),
                   (uint32_t)h[2] | ((uint32_t)h[3] << 16));
    L = make_uint2((uint32_t)l[0] | ((uint32_t)l[1] << 16),
                   (uint32_t)l[2] | ((uint32_t)l[3] << 16));
}

// ---------------- CSR build --------------------------------------------------
__global__ void k_count(const int* __restrict__ src, const int* __restrict__ dst) {
    int e = blockIdx.x * blockDim.x + threadIdx.x;
    if (e < NE) {
        atomicAdd(&g_indeg_i [dst[e]], 1);
        atomicAdd(&g_outdeg_i[src[e]], 1);
    }
}

__global__ void k_scan1() {
    __shared__ int swarp[8];
    int t = threadIdx.x, b = blockIdx.x;
    int i = b * 256 + t;
    int v = (i < NN) ? g_indeg_i[i] : 0;
    int x = v;
    int lane = t & 31, w = t >> 5;
#pragma unroll
    for (int o = 1; o < 32; o <<= 1) {
        int y = __shfl_up_sync(0xffffffffu, x, o);
        if (lane >= o) x += y;
    }
    if (lane == 31) swarp[w] = x;
    __syncthreads();
    if (w == 0) {
        int s = (lane < 8) ? swarp[lane] : 0;
#pragma unroll
        for (int o = 1; o < 8; o <<= 1) {
            int y = __shfl_up_sync(0xffffffffu, s, o);
            if (lane >= o) s += y;
        }
        if (lane < 8) swarp[lane] = s;
    }
    __syncthreads();
    int off = (w > 0) ? swarp[w - 1] : 0;
    if (i < NN) g_rowstart[i] = x - v + off;
    if (t == 255) g_blksum[b] = x + off;
}

__global__ void k_scan2() {
    __shared__ int swarp[16];
    int t = threadIdx.x;
    int v = (t < NB) ? g_blksum[t] : 0;
    int x = v;
    int lane = t & 31, w = t >> 5;
#pragma unroll
    for (int o = 1; o < 32; o <<= 1) {
        int y = __shfl_up_sync(0xffffffffu, x, o);
        if (lane >= o) x += y;
    }
    if (lane == 31) swarp[w] = x;
    __syncthreads();
    if (w == 0) {
        int s = (lane < 16) ? swarp[lane] : 0;
#pragma unroll
        for (int o = 1; o < 16; o <<= 1) {
            int y = __shfl_up_sync(0xffffffffu, s, o);
            if (lane >= o) s += y;
        }
        if (lane < 16) swarp[lane] = s;
    }
    __syncthreads();
    int off = (w > 0) ? swarp[w - 1] : 0;
    if (t < NB) g_blksum[t] = x - v + off;
}

__global__ void k_scan3() {
    int i = blockIdx.x * 256 + threadIdx.x;
    if (i < NN) {
        int r = g_rowstart[i] + g_blksum[blockIdx.x];
        g_rowstart[i] = r;
        g_cursor[i]   = r;
        g_rin[i]      = rsqrtf(fmaxf((float)g_indeg_i[i], 1.0f));
    }
}

__global__ void k_scatter(const int* __restrict__ src, const int* __restrict__ dst,
                          const int* __restrict__ eattr) {
    int e = blockIdx.x * blockDim.x + threadIdx.x;
    if (e < NE) {
        int d = dst[e];
        int pos = atomicAdd(&g_cursor[d], 1);
        g_csr[pos] = (unsigned)src[e] | ((unsigned)eattr[e] << 17);
    }
}

// ---------------- weights -> bf16 hi/lo B^T images --------------------------
__global__ void k_wprep(const float* __restrict__ w1, const float* __restrict__ w2,
                        const float* __restrict__ v) {
    int idx = blockIdx.x * 256 + threadIdx.x;
    if (idx >= 12288) return;
    int mat = idx >> 12;
    int rem = idx & 4095;
    int o  = rem >> 5;
    int k0 = (rem & 31) * 4;
    const float* src = (mat == 0) ? w1 : (mat == 1) ? w2 : v;
    __nv_bfloat16* hi = (mat == 0) ? g_w1h : (mat == 1) ? g_w2h : g_vh;
    __nv_bfloat16* lo = (mat == 0) ? g_w1l : (mat == 1) ? g_w2l : g_vl;
    float4 x;
    x.x = src[(size_t)(k0 + 0) * F + o];
    x.y = src[(size_t)(k0 + 1) * F + o];
    x.z = src[(size_t)(k0 + 2) * F + o];
    x.w = src[(size_t)(k0 + 3) * F + o];
    uint2 H, L; split4(x, H, L);
    *reinterpret_cast<uint2*>(&hi[o * F + k0]) = H;
    *reinterpret_cast<uint2*>(&lo[o * F + k0]) = L;
}

// ---------------- fused dual node GEMM via mma.sync -------------------------
__global__ __launch_bounds__(256, 1) void k_node_mma(const float* __restrict__ feat,
                                                     const float* __restrict__ w2full) {
    extern __shared__ __align__(16) unsigned char smem[];
    __nv_bfloat16* Ah = (__nv_bfloat16*)smem;
    __nv_bfloat16* Al = Ah + 128 * LDA;
    __nv_bfloat16* Bw[4];
    Bw[0] = Al    + 128 * LDA;
    Bw[1] = Bw[0] + 128 * LDA;
    Bw[2] = Bw[1] + 128 * LDA;
    Bw[3] = Bw[2] + 128 * LDA;

    const int tid = threadIdx.x, lane = tid & 31, wid = tid >> 5;
    const int bid = blockIdx.x;

    {
        int r = tid >> 1, hf = tid & 1;
        int n = bid * 128 + r;
        float s = 0.0f;
        if (n < NN) s = rsqrtf(fmaxf((float)g_outdeg_i[n], 1.0f));
#pragma unroll
        for (int q = 0; q < 16; q++) {
            int k0 = hf * 64 + q * 4;
            float4 x = make_float4(0.f, 0.f, 0.f, 0.f);
            if (n < NN) {
                x = *reinterpret_cast<const float4*>(&feat[(size_t)n * F + k0]);
                x.x *= s; x.y *= s; x.z *= s; x.w *= s;
            }
            uint2 H, L; split4(x, H, L);
            *reinterpret_cast<uint2*>(&Ah[r * LDA + k0]) = H;
            *reinterpret_cast<uint2*>(&Al[r * LDA + k0]) = L;
        }
    }
    {
        const uint4* s0 = (const uint4*)g_w1h; const uint4* s1 = (const uint4*)g_w1l;
        const uint4* s2 = (const uint4*)g_w2h; const uint4* s3 = (const uint4*)g_w2l;
#pragma unroll
        for (int i = 0; i < 8; i++) {
            int idx = tid + i * 256;
            int row = idx >> 4, col = idx & 15;
            ((uint4*)Bw[0])[row * 17 + col] = s0[idx];
            ((uint4*)Bw[1])[row * 17 + col] = s1[idx];
            ((uint4*)Bw[2])[row * 17 + col] = s2[idx];
            ((uint4*)Bw[3])[row * 17 + col] = s3[idx];
        }
    }
    __syncthreads();

    const int warp_m = wid & 1, warp_n = wid >> 1;
    const uint32_t sbase = smem_to_u32(smem);
    const uint32_t aAh = sbase, aAl = sbase + REG_BYTES;
    const int nl0 = (warp_n & 1) * 64;

    float c[4][8][4];
#pragma unroll
    for (int i = 0; i < 4; i++)
#pragma unroll
        for (int j = 0; j < 8; j++)
#pragma unroll
            for (int q = 0; q < 4; q++) c[i][j][q] = 0.f;

#pragma unroll 1
    for (int p = 0; p < 3; p++) {
        uint32_t Abase = (p == 2) ? aAl : aAh;
        uint32_t Bbase = sbase + (uint32_t)(2 + 2 * (warp_n >> 1) + (p == 1)) * REG_BYTES;
#pragma unroll
        for (int ks = 0; ks < 8; ks++) {
            int k0 = ks * 16;
            uint32_t a[4][4];
#pragma unroll
            for (int i = 0; i < 4; i++) {
                int row = warp_m * 64 + i * 16 + (lane & 15);
                ldsm4(a[i][0], a[i][1], a[i][2], a[i][3],
                      Abase + (uint32_t)(row * LDA + k0 + ((lane >> 4) << 3)) * 2);
            }
            uint32_t b[8][2];
#pragma unroll
            for (int jj = 0; jj < 4; jj++) {
                int o = nl0 + jj * 16 + (lane & 7) + ((lane >> 4) << 3);
                uint32_t r0, r1, r2, r3;
                ldsm4(r0, r1, r2, r3,
                      Bbase + (uint32_t)(o * LDA + k0 + (((lane >> 3) & 1) << 3)) * 2);
                b[jj * 2][0] = r0; b[jj * 2][1] = r1;
                b[jj * 2 + 1][0] = r2; b[jj * 2 + 1][1] = r3;
            }
#pragma unroll
            for (int i = 0; i < 4; i++)
#pragma unroll
                for (int j = 0; j < 8; j++)
                    mma_bf16(c[i][j], a[i], b[j]);
        }
    }

    const int colbase = warp_n * 64;
#pragma unroll
    for (int i = 0; i < 4; i++) {
        int r0 = warp_m * 64 + i * 16 + (lane >> 2);
        int n0 = bid * 128 + r0;
        int n1 = n0 + 8;
#pragma unroll
        for (int j = 0; j < 8; j++) {
            int col = colbase + j * 8 + (lane & 3) * 2;
            if (col < 128) {
                if (n0 < NN)
                    *reinterpret_cast<float2*>(&g_hsum[(size_t)n0 * F + col]) =
                        make_float2(c[i][j][0], c[i][j][1]);
                if (n1 < NN)
                    *reinterpret_cast<float2*>(&g_hsum[(size_t)n1 * F + col]) =
                        make_float2(c[i][j][2], c[i][j][3]);
            } else {
                int c2 = col - 128;
                float2 bias = *reinterpret_cast<const float2*>(&w2full[(size_t)128 * F + c2]);
                if (n0 < NN)
                    *reinterpret_cast<float2*>(&g_hprod[(size_t)n0 * F + c2]) =
                        make_float2(tanhf(c[i][j][0] + bias.x), tanhf(c[i][j][1] + bias.y));
                if (n1 < NN)
                    *reinterpret_cast<float2*>(&g_hprod[(size_t)n1 * F + c2]) =
                        make_float2(tanhf(c[i][j][2] + bias.x), tanhf(c[i][j][3] + bias.y));
            }
        }
    }
}

// ---------------- fused gather + final GEMM ---------------------------------
// Phase 1 (16 warps, 8 nodes each): register-accumulate sum & log-prod over
// CSR neighbors; write `as` (fp32) and bf16-split hp into smem.
// Phase 2: 128x128 MMA with v (3-pass split), epilogue out=(as+C)*rin.
__global__ __launch_bounds__(512, 1) void k_fused(const float* __restrict__ bond,
                                                  float* __restrict__ out) {
    extern __shared__ __align__(16) unsigned char smem[];
    float*        As = (float*)(smem + AS_OFF);
    __nv_bfloat16* Ah = (__nv_bfloat16*)(smem + AH_OFF);
    __nv_bfloat16* Al = (__nv_bfloat16*)(smem + AL_OFF);

    const int tid = threadIdx.x, lane = tid & 31, wid = tid >> 5;
    const int bid = blockIdx.x;
    const int g = lane;

    // B tiles (v hi/lo) -> smem
    {
        const uint4* s0 = (const uint4*)g_vh;
        const uint4* s1 = (const uint4*)g_vl;
        uint4* d0 = (uint4*)(smem + BH_OFF);
        uint4* d1 = (uint4*)(smem + BL_OFF);
#pragma unroll
        for (int i = 0; i < 4; i++) {
            int idx = tid + i * 512;
            int row = idx >> 4, col = idx & 15;
            d0[row * 17 + col] = s0[idx];
            d1[row * 17 + col] = s1[idx];
        }
    }

    const float4* hs4 = (const float4*)g_hsum;
    const float4* hp4 = (const float4*)g_hprod;
    const float4* bd4 = (const float4*)bond;

    // Phase 1: gather. warp wid -> rows wid*8 .. wid*8+7
#pragma unroll 1
    for (int q = 0; q < 8; q++) {
        int r = wid * 8 + q;
        int n = bid * 128 + r;

        float4 as = make_float4(0.f, 0.f, 0.f, 0.f);
        float4 al = make_float4(0.f, 0.f, 0.f, 0.f);
        unsigned sg = 0;

        if (n < NN) {
            int base = g_rowstart[n];
            int deg  = g_indeg_i[n];
            int i = 0;
            for (; i + 4 <= deg; i += 4) {
                unsigned c0 = __ldg(&g_csr[base + i]);
                unsigned c1 = __ldg(&g_csr[base + i + 1]);
                unsigned c2 = __ldg(&g_csr[base + i + 2]);
                unsigned c3 = __ldg(&g_csr[base + i + 3]);
                int s0 = c0 & 0x1FFFF, a0 = c0 >> 17;
                int s1 = c1 & 0x1FFFF, a1 = c1 >> 17;
                int s2 = c2 & 0x1FFFF, a2 = c2 >> 17;
                int s3 = c3 & 0x1FFFF, a3 = c3 >> 17;
                float4 e0 = __ldg(bd4 + (size_t)a0 * 32 + g);
                float4 e1 = __ldg(bd4 + (size_t)a1 * 32 + g);
                float4 e2 = __ldg(bd4 + (size_t)a2 * 32 + g);
                float4 e3 = __ldg(bd4 + (size_t)a3 * 32 + g);
                float4 h0 = __ldg(hs4 + (size_t)s0 * 32 + g);
                float4 h1 = __ldg(hs4 + (size_t)s1 * 32 + g);
                float4 h2 = __ldg(hs4 + (size_t)s2 * 32 + g);
                float4 h3 = __ldg(hs4 + (size_t)s3 * 32 + g);
                float4 p0 = __ldg(hp4 + (size_t)s0 * 32 + g);
                float4 p1 = __ldg(hp4 + (size_t)s1 * 32 + g);
                float4 p2 = __ldg(hp4 + (size_t)s2 * 32 + g);
                float4 p3 = __ldg(hp4 + (size_t)s3 * 32 + g);

                as.x += h0.x*e0.x + h1.x*e1.x + h2.x*e2.x + h3.x*e3.x;
                as.y += h0.y*e0.y + h1.y*e1.y + h2.y*e2.y + h3.y*e3.y;
                as.z += h0.z*e0.z + h1.z*e1.z + h2.z*e2.z + h3.z*e3.z;
                as.w += h0.w*e0.w + h1.w*e1.w + h2.w*e2.w + h3.w*e3.w;

                float4 m0 = make_float4(p0.x*e0.x, p0.y*e0.y, p0.z*e0.z, p0.w*e0.w);
                float4 m1 = make_float4(p1.x*e1.x, p1.y*e1.y, p1.z*e1.z, p1.w*e1.w);
                float4 m2 = make_float4(p2.x*e2.x, p2.y*e2.y, p2.z*e2.z, p2.w*e2.w);
                float4 m3 = make_float4(p3.x*e3.x, p3.y*e3.y, p3.z*e3.z, p3.w*e3.w);
                al.x += __logf(fabsf(m0.x)) + __logf(fabsf(m1.x))
                      + __logf(fabsf(m2.x)) + __logf(fabsf(m3.x));
                al.y += __logf(fabsf(m0.y)) + __logf(fabsf(m1.y))
                      + __logf(fabsf(m2.y)) + __logf(fabsf(m3.y));
                al.z += __logf(fabsf(m0.z)) + __logf(fabsf(m1.z))
                      + __logf(fabsf(m2.z)) + __logf(fabsf(m3.z));
                al.w += __logf(fabsf(m0.w)) + __logf(fabsf(m1.w))
                      + __logf(fabsf(m2.w)) + __logf(fabsf(m3.w));
                unsigned t0 =  ((__float_as_uint(m0.x) >> 31) & 1u)
                            | (((__float_as_uint(m0.y) >> 31) & 1u) << 1)
                            | (((__float_as_uint(m0.z) >> 31) & 1u) << 2)
                            | (((__float_as_uint(m0.w) >> 31) & 1u) << 3);
                unsigned t1 =  ((__float_as_uint(m1.x) >> 31) & 1u)
                            | (((__float_as_uint(m1.y) >> 31) & 1u) << 1)
                            | (((__float_as_uint(m1.z) >> 31) & 1u) << 2)
                            | (((__float_as_uint(m1.w) >> 31) & 1u) << 3);
                unsigned t2 =  ((__float_as_uint(m2.x) >> 31) & 1u)
                            | (((__float_as_uint(m2.y) >> 31) & 1u) << 1)
                            | (((__float_as_uint(m2.z) >> 31) & 1u) << 2)
                            | (((__float_as_uint(m2.w) >> 31) & 1u) << 3);
                unsigned t3 =  ((__float_as_uint(m3.x) >> 31) & 1u)
                            | (((__float_as_uint(m3.y) >> 31) & 1u) << 1)
                            | (((__float_as_uint(m3.z) >> 31) & 1u) << 2)
                            | (((__float_as_uint(m3.w) >> 31) & 1u) << 3);
                sg ^= t0 ^ t1 ^ t2 ^ t3;
            }
            for (; i < deg; i++) {
                unsigned c0 = __ldg(&g_csr[base + i]);
                int s0 = c0 & 0x1FFFF, a0 = c0 >> 17;
                float4 e0 = __ldg(bd4 + (size_t)a0 * 32 + g);
                float4 h0 = __ldg(hs4 + (size_t)s0 * 32 + g);
                float4 p0 = __ldg(hp4 + (size_t)s0 * 32 + g);
                as.x += h0.x*e0.x; as.y += h0.y*e0.y;
                as.z += h0.z*e0.z; as.w += h0.w*e0.w;
                float4 m0 = make_float4(p0.x*e0.x, p0.y*e0.y, p0.z*e0.z, p0.w*e0.w);
                al.x += __logf(fabsf(m0.x));
                al.y += __logf(fabsf(m0.y));
                al.z += __logf(fabsf(m0.z));
                al.w += __logf(fabsf(m0.w));
                sg ^=  ((__float_as_uint(m0.x) >> 31) & 1u)
                    | (((__float_as_uint(m0.y) >> 31) & 1u) << 1)
                    | (((__float_as_uint(m0.z) >> 31) & 1u) << 2)
                    | (((__float_as_uint(m0.w) >> 31) & 1u) << 3);
            }
        }

        // as -> smem
        *reinterpret_cast<float4*>(&As[r * 128 + g * 4]) = as;

        // hp = sign*exp(al) -> bf16 split -> Ah/Al
        float4 hp = make_float4(0.f, 0.f, 0.f, 0.f);
        if (n < NN) {
            hp.x = __expf(al.x); if (sg & 1u) hp.x = -hp.x;
            hp.y = __expf(al.y); if (sg & 2u) hp.y = -hp.y;
            hp.z = __expf(al.z); if (sg & 4u) hp.z = -hp.z;
            hp.w = __expf(al.w); if (sg & 8u) hp.w = -hp.w;
        }
        uint2 H, L; split4(hp, H, L);
        *reinterpret_cast<uint2*>(&Ah[r * LDA + g * 4]) = H;
        *reinterpret_cast<uint2*>(&Al[r * LDA + g * 4]) = L;
    }
    __syncthreads();

    // Phase 2: MMA 128x128, 16 warps (4x4 of 32x32 tiles)
    const int warp_m = wid & 3, warp_n = wid >> 2;
    const uint32_t sbase = smem_to_u32(smem);
    const int nl0 = warp_n * 32;

    float c[2][4][4];
#pragma unroll
    for (int i = 0; i < 2; i++)
#pragma unroll
        for (int j = 0; j < 4; j++)
#pragma unroll
            for (int q = 0; q < 4; q++) c[i][j][q] = 0.f;

#pragma unroll 1
    for (int p = 0; p < 3; p++) {
        uint32_t Abase = sbase + ((p == 2) ? AL_OFF : AH_OFF);
        uint32_t Bbase = sbase + ((p == 1) ? BL_OFF : BH_OFF);
#pragma unroll
        for (int ks = 0; ks < 8; ks++) {
            int k0 = ks * 16;
            uint32_t a[2][4];
#pragma unroll
            for (int i = 0; i < 2; i++) {
                int row = warp_m * 32 + i * 16 + (lane & 15);
                ldsm4(a[i][0], a[i][1], a[i][2], a[i][3],
                      Abase + (uint32_t)(row * LDA + k0 + ((lane >> 4) << 3)) * 2);
            }
            uint32_t b[4][2];
#pragma unroll
            for (int jj = 0; jj < 2; jj++) {
                int o = nl0 + jj * 16 + (lane & 7) + ((lane >> 4) << 3);
                uint32_t r0, r1, r2, r3;
                ldsm4(r0, r1, r2, r3,
                      Bbase + (uint32_t)(o * LDA + k0 + (((lane >> 3) & 1) << 3)) * 2);
                b[jj * 2][0] = r0; b[jj * 2][1] = r1;
                b[jj * 2 + 1][0] = r2; b[jj * 2 + 1][1] = r3;
            }
#pragma unroll
            for (int i = 0; i < 2; i++)
#pragma unroll
                for (int j = 0; j < 4; j++)
                    mma_bf16(c[i][j], a[i], b[j]);
        }
    }

    // epilogue: out = (As + C) * rin, single store
#pragma unroll
    for (int i = 0; i < 2; i++) {
        int r0 = warp_m * 32 + i * 16 + (lane >> 2);
        int r1 = r0 + 8;
        int n0 = bid * 128 + r0;
        int n1 = n0 + 8;
        float rin0 = (n0 < NN) ? g_rin[n0] : 0.f;
        float rin1 = (n1 < NN) ? g_rin[n1] : 0.f;
#pragma unroll
        for (int j = 0; j < 4; j++) {
            int col = nl0 + j * 8 + (lane & 3) * 2;
            if (n0 < NN) {
                float2 prev = *reinterpret_cast<float2*>(&As[r0 * 128 + col]);
                *reinterpret_cast<float2*>(&out[(size_t)n0 * F + col]) =
                    make_float2((prev.x + c[i][j][0]) * rin0,
                                (prev.y + c[i][j][1]) * rin0);
            }
            if (n1 < NN) {
                float2 prev = *reinterpret_cast<float2*>(&As[r1 * 128 + col]);
                *reinterpret_cast<float2*>(&out[(size_t)n1 * F + col]) =
                    make_float2((prev.x + c[i][j][2]) * rin1,
                                (prev.y + c[i][j][3]) * rin1);
            }
        }
    }
}

// ---------------- launcher ---------------------------------------------------
#define SMEM_NODE (6 * REG_BYTES)

extern "C" void kernel_launch(void* const* d_in, const int* in_sizes, int n_in,
                              void* d_out, int out_size) {
    const float* feat  = (const float*)d_in[0];
    const int*   src   = (const int*)  d_in[1];
    const int*   dst   = (const int*)  d_in[2];
    const int*   eattr = (const int*)  d_in[3];
    const float* w1    = (const float*)d_in[4];
    const float* w2    = (const float*)d_in[5];
    const float* v     = (const float*)d_in[6];
    const float* bond  = (const float*)d_in[7];
    float* out = (float*)d_out;

    cudaFuncSetAttribute(k_node_mma, cudaFuncAttributeMaxDynamicSharedMemorySize, SMEM_NODE);
    cudaFuncSetAttribute(k_fused,    cudaFuncAttributeMaxDynamicSharedMemorySize, SMEM_FUSED);

    void *p_id, *p_od;
    cudaGetSymbolAddress(&p_id, g_indeg_i);
    cudaGetSymbolAddress(&p_od, g_outdeg_i);
    cudaMemsetAsync(p_id, 0, NN * sizeof(int));
    cudaMemsetAsync(p_od, 0, NN * sizeof(int));

    k_count    <<<(NE + 255) / 256, 256>>>(src, dst);
    k_scan1    <<<NB, 256>>>();
    k_scan2    <<<1, 512>>>();
    k_scan3    <<<NB, 256>>>();
    k_wprep    <<<48, 256>>>(w1, w2, v);
    k_scatter  <<<(NE + 255) / 256, 256>>>(src, dst, eattr);
    k_node_mma <<<NT, 256, SMEM_NODE>>>(feat, w2);
    k_fused    <<<NT, 512, SMEM_FUSED>>>(bond, out);
}

// round 9
// speedup vs baseline: 1.1639x; 1.1639x over previous
#include <cuda_runtime.h>
#include <cuda_bf16.h>
#include <cstdint>

#define NN 100000
#define NE 800000
#define F  128
#define NT 782              // ceil(NN/128) node tiles
#define NB 391              // ceil(NN/256) scan blocks
#define LDA 136             // smem row stride in bf16 elements
#define REG_BYTES (128 * LDA * 2)   // 34816

// fused kernel smem layout (bytes)
#define AS_OFF 0
#define AH_OFF 65536
#define AL_OFF (AH_OFF + REG_BYTES)
#define BH_OFF (AL_OFF + REG_BYTES)
#define BL_OFF (BH_OFF + REG_BYTES)
#define SMEM_FUSED (BL_OFF + REG_BYTES)   // 204800

// ---------------- scratch ----------------------------------------------------
__device__ int      g_indeg_i [NN];
__device__ int      g_outdeg_i[NN];
__device__ int      g_rowstart[NN];
__device__ int      g_cursor  [NN];
__device__ float    g_rin     [NN];
__device__ int      g_blksum  [512];
__device__ unsigned g_csr     [NE];
__device__ float    g_hsum [(size_t)NN * F];
__device__ float    g_hprod[(size_t)NN * F];
__device__ __nv_bfloat16 g_w1h[F * F], g_w1l[F * F];
__device__ __nv_bfloat16 g_w2h[F * F], g_w2l[F * F];
__device__ __nv_bfloat16 g_vh [F * F], g_vl [F * F];

// ---------------- helpers ----------------------------------------------------
__device__ __forceinline__ uint32_t smem_to_u32(const void* p) {
    uint32_t a;
    asm("{ .reg .u64 t; cvta.to.shared.u64 t, %1; cvt.u32.u64 %0, t; }" : "=r"(a) : "l"(p));
    return a;
}

__device__ __forceinline__ void ldsm4(uint32_t& r0, uint32_t& r1, uint32_t& r2, uint32_t& r3,
                                      uint32_t addr) {
    asm volatile("ldmatrix.sync.aligned.m8n8.x4.shared.b16 {%0,%1,%2,%3}, [%4];"
                 : "=r"(r0), "=r"(r1), "=r"(r2), "=r"(r3) : "r"(addr));
}

__device__ __forceinline__ void mma_bf16(float* c, const uint32_t* a, const uint32_t* b) {
    asm volatile("mma.sync.aligned.m16n8k16.row.col.f32.bf16.bf16.f32 "
                 "{%0,%1,%2,%3}, {%4,%5,%6,%7}, {%8,%9}, {%0,%1,%2,%3};"
                 : "+f"(c[0]), "+f"(c[1]), "+f"(c[2]), "+f"(c[3])
                 : "r"(a[0]), "r"(a[1]), "r"(a[2]), "r"(a[3]), "r"(b[0]), "r"(b[1]));
}

__device__ __forceinline__ void split4(float4 x, uint2& H, uint2& L) {
    float xs[4] = {x.x, x.y, x.z, x.w};
    unsigned short h[4], l[4];
#pragma unroll
    for (int j = 0; j < 4; j++) {
        __nv_bfloat16 bh = __float2bfloat16(xs[j]);
        float r = xs[j] - __bfloat162float(bh);
        __nv_bfloat16 bl = __float2bfloat16(r);
        h[j] = __bfloat16_as_ushort(bh);
        l[j] = __bfloat16_as_ushort(bl);
    }
    H = make_uint2((uint32_t)h[0] | ((uint32_t)h[1] << 16),
                   (uint32_t)h[2] | ((uint32_t)h[3] << 16));
    L = make_uint2((uint32_t)l[0] | ((uint32_t)l[1] << 16),
                   (uint32_t)l[2] | ((uint32_t)l[3] << 16));
}

// ---------------- CSR build --------------------------------------------------
__global__ void k_count(const int* __restrict__ src, const int* __restrict__ dst) {
    int e = blockIdx.x * blockDim.x + threadIdx.x;
    if (e < NE) {
        atomicAdd(&g_indeg_i [dst[e]], 1);
        atomicAdd(&g_outdeg_i[src[e]], 1);
    }
}

__global__ void k_scan1() {
    __shared__ int swarp[8];
    int t = threadIdx.x, b = blockIdx.x;
    int i = b * 256 + t;
    int v = (i < NN) ? g_indeg_i[i] : 0;
    int x = v;
    int lane = t & 31, w = t >> 5;
#pragma unroll
    for (int o = 1; o < 32; o <<= 1) {
        int y = __shfl_up_sync(0xffffffffu, x, o);
        if (lane >= o) x += y;
    }
    if (lane == 31) swarp[w] = x;
    __syncthreads();
    if (w == 0) {
        int s = (lane < 8) ? swarp[lane] : 0;
#pragma unroll
        for (int o = 1; o < 8; o <<= 1) {
            int y = __shfl_up_sync(0xffffffffu, s, o);
            if (lane >= o) s += y;
        }
        if (lane < 8) swarp[lane] = s;
    }
    __syncthreads();
    int off = (w > 0) ? swarp[w - 1] : 0;
    if (i < NN) g_rowstart[i] = x - v + off;
    if (t == 255) g_blksum[b] = x + off;
}

__global__ void k_scan2() {
    __shared__ int swarp[16];
    int t = threadIdx.x;
    int v = (t < NB) ? g_blksum[t] : 0;
    int x = v;
    int lane = t & 31, w = t >> 5;
#pragma unroll
    for (int o = 1; o < 32; o <<= 1) {
        int y = __shfl_up_sync(0xffffffffu, x, o);
        if (lane >= o) x += y;
    }
    if (lane == 31) swarp[w] = x;
    __syncthreads();
    if (w == 0) {
        int s = (lane < 16) ? swarp[lane] : 0;
#pragma unroll
        for (int o = 1; o < 16; o <<= 1) {
            int y = __shfl_up_sync(0xffffffffu, s, o);
            if (lane >= o) s += y;
        }
        if (lane < 16) swarp[lane] = s;
    }
    __syncthreads();
    int off = (w > 0) ? swarp[w - 1] : 0;
    if (t < NB) g_blksum[t] = x - v + off;
}

__global__ void k_scan3() {
    int i = blockIdx.x * 256 + threadIdx.x;
    if (i < NN) {
        int r = g_rowstart[i] + g_blksum[blockIdx.x];
        g_rowstart[i] = r;
        g_cursor[i]   = r;
        g_rin[i]      = rsqrtf(fmaxf((float)g_indeg_i[i], 1.0f));
    }
}

__global__ void k_scatter(const int* __restrict__ src, const int* __restrict__ dst,
                          const int* __restrict__ eattr) {
    int e = blockIdx.x * blockDim.x + threadIdx.x;
    if (e < NE) {
        int d = dst[e];
        int pos = atomicAdd(&g_cursor[d], 1);
        g_csr[pos] = (unsigned)src[e] | ((unsigned)eattr[e] << 17);
    }
}

// ---------------- weights -> bf16 hi/lo B^T images --------------------------
__global__ void k_wprep(const float* __restrict__ w1, const float* __restrict__ w2,
                        const float* __restrict__ v) {
    int idx = blockIdx.x * 256 + threadIdx.x;
    if (idx >= 12288) return;
    int mat = idx >> 12;
    int rem = idx & 4095;
    int o  = rem >> 5;
    int k0 = (rem & 31) * 4;
    const float* src = (mat == 0) ? w1 : (mat == 1) ? w2 : v;
    __nv_bfloat16* hi = (mat == 0) ? g_w1h : (mat == 1) ? g_w2h : g_vh;
    __nv_bfloat16* lo = (mat == 0) ? g_w1l : (mat == 1) ? g_w2l : g_vl;
    float4 x;
    x.x = src[(size_t)(k0 + 0) * F + o];
    x.y = src[(size_t)(k0 + 1) * F + o];
    x.z = src[(size_t)(k0 + 2) * F + o];
    x.w = src[(size_t)(k0 + 3) * F + o];
    uint2 H, L; split4(x, H, L);
    *reinterpret_cast<uint2*>(&hi[o * F + k0]) = H;
    *reinterpret_cast<uint2*>(&lo[o * F + k0]) = L;
}

// ---------------- fused dual node GEMM via mma.sync (512 threads) -----------
// C[128 x 256] = A'[128 x 384] @ [W1' | W2'][384 x 256]; 16 warps, 64x32 tiles
__global__ __launch_bounds__(512, 1) void k_node_mma(const float* __restrict__ feat,
                                                     const float* __restrict__ w2full) {
    extern __shared__ __align__(16) unsigned char smem[];
    __nv_bfloat16* Ah = (__nv_bfloat16*)smem;
    __nv_bfloat16* Al = Ah + 128 * LDA;
    __nv_bfloat16* Bw[4];
    Bw[0] = Al    + 128 * LDA;
    Bw[1] = Bw[0] + 128 * LDA;
    Bw[2] = Bw[1] + 128 * LDA;
    Bw[3] = Bw[2] + 128 * LDA;

    const int tid = threadIdx.x, lane = tid & 31, wid = tid >> 5;
    const int bid = blockIdx.x;

    // fill A: feat * outdeg^-1/2 -> bf16 hi/lo; 4 threads per row
    {
        int r = tid >> 2, hf = tid & 3;
        int n = bid * 128 + r;
        float s = 0.0f;
        if (n < NN) s = rsqrtf(fmaxf((float)g_outdeg_i[n], 1.0f));
#pragma unroll
        for (int q = 0; q < 8; q++) {
            int k0 = hf * 32 + q * 4;
            float4 x = make_float4(0.f, 0.f, 0.f, 0.f);
            if (n < NN) {
                x = *reinterpret_cast<const float4*>(&feat[(size_t)n * F + k0]);
                x.x *= s; x.y *= s; x.z *= s; x.w *= s;
            }
            uint2 H, L; split4(x, H, L);
            *reinterpret_cast<uint2*>(&Ah[r * LDA + k0]) = H;
            *reinterpret_cast<uint2*>(&Al[r * LDA + k0]) = L;
        }
    }
    {
        const uint4* s0 = (const uint4*)g_w1h; const uint4* s1 = (const uint4*)g_w1l;
        const uint4* s2 = (const uint4*)g_w2h; const uint4* s3 = (const uint4*)g_w2l;
#pragma unroll
        for (int i = 0; i < 4; i++) {
            int idx = tid + i * 512;
            int row = idx >> 4, col = idx & 15;
            ((uint4*)Bw[0])[row * 17 + col] = s0[idx];
            ((uint4*)Bw[1])[row * 17 + col] = s1[idx];
            ((uint4*)Bw[2])[row * 17 + col] = s2[idx];
            ((uint4*)Bw[3])[row * 17 + col] = s3[idx];
        }
    }
    __syncthreads();

    const int warp_m = wid & 1, warp_n = wid >> 1;    // 2 x 8, warp tile 64x32
    const uint32_t sbase = smem_to_u32(smem);
    const uint32_t aAh = sbase, aAl = sbase + REG_BYTES;
    const int nl0 = (warp_n & 3) * 32;

    float c[4][4][4];
#pragma unroll
    for (int i = 0; i < 4; i++)
#pragma unroll
        for (int j = 0; j < 4; j++)
#pragma unroll
            for (int q = 0; q < 4; q++) c[i][j][q] = 0.f;

#pragma unroll 1
    for (int p = 0; p < 3; p++) {
        uint32_t Abase = (p == 2) ? aAl : aAh;
        uint32_t Bbase = sbase + (uint32_t)(2 + 2 * (warp_n >> 2) + (p == 1)) * REG_BYTES;
#pragma unroll
        for (int ks = 0; ks < 8; ks++) {
            int k0 = ks * 16;
            uint32_t a[4][4];
#pragma unroll
            for (int i = 0; i < 4; i++) {
                int row = warp_m * 64 + i * 16 + (lane & 15);
                ldsm4(a[i][0], a[i][1], a[i][2], a[i][3],
                      Abase + (uint32_t)(row * LDA + k0 + ((lane >> 4) << 3)) * 2);
            }
            uint32_t b[4][2];
#pragma unroll
            for (int jj = 0; jj < 2; jj++) {
                int o = nl0 + jj * 16 + (lane & 7) + ((lane >> 4) << 3);
                uint32_t r0, r1, r2, r3;
                ldsm4(r0, r1, r2, r3,
                      Bbase + (uint32_t)(o * LDA + k0 + (((lane >> 3) & 1) << 3)) * 2);
                b[jj * 2][0] = r0; b[jj * 2][1] = r1;
                b[jj * 2 + 1][0] = r2; b[jj * 2 + 1][1] = r3;
            }
#pragma unroll
            for (int i = 0; i < 4; i++)
#pragma unroll
                for (int j = 0; j < 4; j++)
                    mma_bf16(c[i][j], a[i], b[j]);
        }
    }

    const int colbase = warp_n * 32;
#pragma unroll
    for (int i = 0; i < 4; i++) {
        int r0 = warp_m * 64 + i * 16 + (lane >> 2);
        int n0 = bid * 128 + r0;
        int n1 = n0 + 8;
#pragma unroll
        for (int j = 0; j < 4; j++) {
            int col = colbase + j * 8 + (lane & 3) * 2;
            if (col < 128) {
                if (n0 < NN)
                    *reinterpret_cast<float2*>(&g_hsum[(size_t)n0 * F + col]) =
                        make_float2(c[i][j][0], c[i][j][1]);
                if (n1 < NN)
                    *reinterpret_cast<float2*>(&g_hsum[(size_t)n1 * F + col]) =
                        make_float2(c[i][j][2], c[i][j][3]);
            } else {
                int c2 = col - 128;
                float2 bias = *reinterpret_cast<const float2*>(&w2full[(size_t)128 * F + c2]);
                if (n0 < NN)
                    *reinterpret_cast<float2*>(&g_hprod[(size_t)n0 * F + c2]) =
                        make_float2(tanhf(c[i][j][0] + bias.x), tanhf(c[i][j][1] + bias.y));
                if (n1 < NN)
                    *reinterpret_cast<float2*>(&g_hprod[(size_t)n1 * F + c2]) =
                        make_float2(tanhf(c[i][j][2] + bias.x), tanhf(c[i][j][3] + bias.y));
            }
        }
    }
}

// ---------------- fused gather + final GEMM (1024 threads) -------------------
__global__ __launch_bounds__(1024, 1) void k_fused(const float* __restrict__ bond,
                                                   float* __restrict__ out) {
    extern __shared__ __align__(16) unsigned char smem[];
    float*        As = (float*)(smem + AS_OFF);
    __nv_bfloat16* Ah = (__nv_bfloat16*)(smem + AH_OFF);
    __nv_bfloat16* Al = (__nv_bfloat16*)(smem + AL_OFF);

    const int tid = threadIdx.x, lane = tid & 31, wid = tid >> 5;
    const int bid = blockIdx.x;
    const int g = lane;

    // B tiles (v hi/lo) -> smem
    {
        const uint4* s0 = (const uint4*)g_vh;
        const uint4* s1 = (const uint4*)g_vl;
        uint4* d0 = (uint4*)(smem + BH_OFF);
        uint4* d1 = (uint4*)(smem + BL_OFF);
#pragma unroll
        for (int i = 0; i < 2; i++) {
            int idx = tid + i * 1024;
            int row = idx >> 4, col = idx & 15;
            d0[row * 17 + col] = s0[idx];
            d1[row * 17 + col] = s1[idx];
        }
    }

    const float4* hs4 = (const float4*)g_hsum;
    const float4* hp4 = (const float4*)g_hprod;
    const float4* bd4 = (const float4*)bond;

    // Phase 1: gather. 32 warps, 4 nodes each
#pragma unroll 1
    for (int q = 0; q < 4; q++) {
        int r = wid * 4 + q;
        int n = bid * 128 + r;

        float4 as = make_float4(0.f, 0.f, 0.f, 0.f);
        float4 al = make_float4(0.f, 0.f, 0.f, 0.f);
        unsigned sg = 0;

        if (n < NN) {
            int base = g_rowstart[n];
            int deg  = g_indeg_i[n];
            int i = 0;
            for (; i + 2 <= deg; i += 2) {
                unsigned c0 = __ldg(&g_csr[base + i]);
                unsigned c1 = __ldg(&g_csr[base + i + 1]);
                int s0 = c0 & 0x1FFFF, a0 = c0 >> 17;
                int s1 = c1 & 0x1FFFF, a1 = c1 >> 17;
                float4 e0 = __ldg(bd4 + (size_t)a0 * 32 + g);
                float4 e1 = __ldg(bd4 + (size_t)a1 * 32 + g);
                float4 h0 = __ldg(hs4 + (size_t)s0 * 32 + g);
                float4 h1 = __ldg(hs4 + (size_t)s1 * 32 + g);
                float4 p0 = __ldg(hp4 + (size_t)s0 * 32 + g);
                float4 p1 = __ldg(hp4 + (size_t)s1 * 32 + g);

                as.x += h0.x*e0.x + h1.x*e1.x;
                as.y += h0.y*e0.y + h1.y*e1.y;
                as.z += h0.z*e0.z + h1.z*e1.z;
                as.w += h0.w*e0.w + h1.w*e1.w;

                float4 m0 = make_float4(p0.x*e0.x, p0.y*e0.y, p0.z*e0.z, p0.w*e0.w);
                float4 m1 = make_float4(p1.x*e1.x, p1.y*e1.y, p1.z*e1.z, p1.w*e1.w);
                al.x += __logf(fabsf(m0.x)) + __logf(fabsf(m1.x));
                al.y += __logf(fabsf(m0.y)) + __logf(fabsf(m1.y));
                al.z += __logf(fabsf(m0.z)) + __logf(fabsf(m1.z));
                al.w += __logf(fabsf(m0.w)) + __logf(fabsf(m1.w));
                sg ^=  ((__float_as_uint(m0.x) >> 31) & 1u)
                    | (((__float_as_uint(m0.y) >> 31) & 1u) << 1)
                    | (((__float_as_uint(m0.z) >> 31) & 1u) << 2)
                    | (((__float_as_uint(m0.w) >> 31) & 1u) << 3);
                sg ^=  ((__float_as_uint(m1.x) >> 31) & 1u)
                    | (((__float_as_uint(m1.y) >> 31) & 1u) << 1)
                    | (((__float_as_uint(m1.z) >> 31) & 1u) << 2)
                    | (((__float_as_uint(m1.w) >> 31) & 1u) << 3);
            }
            if (i < deg) {
                unsigned c0 = __ldg(&g_csr[base + i]);
                int s0 = c0 & 0x1FFFF, a0 = c0 >> 17;
                float4 e0 = __ldg(bd4 + (size_t)a0 * 32 + g);
                float4 h0 = __ldg(hs4 + (size_t)s0 * 32 + g);
                float4 p0 = __ldg(hp4 + (size_t)s0 * 32 + g);
                as.x += h0.x*e0.x; as.y += h0.y*e0.y;
                as.z += h0.z*e0.z; as.w += h0.w*e0.w;
                float4 m0 = make_float4(p0.x*e0.x, p0.y*e0.y, p0.z*e0.z, p0.w*e0.w);
                al.x += __logf(fabsf(m0.x));
                al.y += __logf(fabsf(m0.y));
                al.z += __logf(fabsf(m0.z));
                al.w += __logf(fabsf(m0.w));
                sg ^=  ((__float_as_uint(m0.x) >> 31) & 1u)
                    | (((__float_as_uint(m0.y) >> 31) & 1u) << 1)
                    | (((__float_as_uint(m0.z) >> 31) & 1u) << 2)
                    | (((__float_as_uint(m0.w) >> 31) & 1u) << 3);
            }
        }

        *reinterpret_cast<float4*>(&As[r * 128 + g * 4]) = as;

        float4 hp = make_float4(0.f, 0.f, 0.f, 0.f);
        if (n < NN) {
            hp.x = __expf(al.x); if (sg & 1u) hp.x = -hp.x;
            hp.y = __expf(al.y); if (sg & 2u) hp.y = -hp.y;
            hp.z = __expf(al.z); if (sg & 4u) hp.z = -hp.z;
            hp.w = __expf(al.w); if (sg & 8u) hp.w = -hp.w;
        }
        uint2 H, L; split4(hp, H, L);
        *reinterpret_cast<uint2*>(&Ah[r * LDA + g * 4]) = H;
        *reinterpret_cast<uint2*>(&Al[r * LDA + g * 4]) = L;
    }
    __syncthreads();

    // Phase 2: MMA 128x128, 32 warps (4 x 8 of 32x16 tiles)
    const int warp_m = wid & 3, warp_n = wid >> 2;
    const uint32_t sbase = smem_to_u32(smem);
    const int nl0 = warp_n * 16;

    float c[2][2][4];
#pragma unroll
    for (int i = 0; i < 2; i++)
#pragma unroll
        for (int j = 0; j < 2; j++)
#pragma unroll
            for (int q = 0; q < 4; q++) c[i][j][q] = 0.f;

#pragma unroll 1
    for (int p = 0; p < 3; p++) {
        uint32_t Abase = sbase + ((p == 2) ? AL_OFF : AH_OFF);
        uint32_t Bbase = sbase + ((p == 1) ? BL_OFF : BH_OFF);
#pragma unroll
        for (int ks = 0; ks < 8; ks++) {
            int k0 = ks * 16;
            uint32_t a[2][4];
#pragma unroll
            for (int i = 0; i < 2; i++) {
                int row = warp_m * 32 + i * 16 + (lane & 15);
                ldsm4(a[i][0], a[i][1], a[i][2], a[i][3],
                      Abase + (uint32_t)(row * LDA + k0 + ((lane >> 4) << 3)) * 2);
            }
            uint32_t b[2][2];
            {
                int o = nl0 + (lane & 7) + ((lane >> 4) << 3);
                uint32_t r0, r1, r2, r3;
                ldsm4(r0, r1, r2, r3,
                      Bbase + (uint32_t)(o * LDA + k0 + (((lane >> 3) & 1) << 3)) * 2);
                b[0][0] = r0; b[0][1] = r1;
                b[1][0] = r2; b[1][1] = r3;
            }
#pragma unroll
            for (int i = 0; i < 2; i++)
#pragma unroll
                for (int j = 0; j < 2; j++)
                    mma_bf16(c[i][j], a[i], b[j]);
        }
    }

    // epilogue: out = (As + C) * rin
#pragma unroll
    for (int i = 0; i < 2; i++) {
        int r0 = warp_m * 32 + i * 16 + (lane >> 2);
        int r1 = r0 + 8;
        int n0 = bid * 128 + r0;
        int n1 = n0 + 8;
        float rin0 = (n0 < NN) ? g_rin[n0] : 0.f;
        float rin1 = (n1 < NN) ? g_rin[n1] : 0.f;
#pragma unroll
        for (int j = 0; j < 2; j++) {
            int col = nl0 + j * 8 + (lane & 3) * 2;
            if (n0 < NN) {
                float2 prev = *reinterpret_cast<float2*>(&As[r0 * 128 + col]);
                *reinterpret_cast<float2*>(&out[(size_t)n0 * F + col]) =
                    make_float2((prev.x + c[i][j][0]) * rin0,
                                (prev.y + c[i][j][1]) * rin0);
            }
            if (n1 < NN) {
                float2 prev = *reinterpret_cast<float2*>(&As[r1 * 128 + col]);
                *reinterpret_cast<float2*>(&out[(size_t)n1 * F + col]) =
                    make_float2((prev.x + c[i][j][2]) * rin1,
                                (prev.y + c[i][j][3]) * rin1);
            }
        }
    }
}

// ---------------- launcher ---------------------------------------------------
#define SMEM_NODE (6 * REG_BYTES)

extern "C" void kernel_launch(void* const* d_in, const int* in_sizes, int n_in,
                              void* d_out, int out_size) {
    const float* feat  = (const float*)d_in[0];
    const int*   src   = (const int*)  d_in[1];
    const int*   dst   = (const int*)  d_in[2];
    const int*   eattr = (const int*)  d_in[3];
    const float* w1    = (const float*)d_in[4];
    const float* w2    = (const float*)d_in[5];
    const float* v     = (const float*)d_in[6];
    const float* bond  = (const float*)d_in[7];
    float* out = (float*)d_out;

    // one-time host resources (created on the first, non-captured call)
    static cudaStream_t s2 = nullptr;
    static cudaEvent_t evFork = nullptr, evJoin = nullptr;
    if (s2 == nullptr) {
        cudaStreamCreateWithFlags(&s2, cudaStreamNonBlocking);
        cudaEventCreateWithFlags(&evFork, cudaEventDisableTiming);
        cudaEventCreateWithFlags(&evJoin, cudaEventDisableTiming);
        cudaFuncSetAttribute(k_node_mma, cudaFuncAttributeMaxDynamicSharedMemorySize, SMEM_NODE);
        cudaFuncSetAttribute(k_fused,    cudaFuncAttributeMaxDynamicSharedMemorySize, SMEM_FUSED);
    }

    void *p_id, *p_od;
    cudaGetSymbolAddress(&p_id, g_indeg_i);
    cudaGetSymbolAddress(&p_od, g_outdeg_i);
    cudaMemsetAsync(p_id, 0, NN * sizeof(int));
    cudaMemsetAsync(p_od, 0, NN * sizeof(int));

    k_count <<<(NE + 255) / 256, 256>>>(src, dst);

    // fork: CSR chain on s2, GEMM chain on default stream
    cudaEventRecord(evFork, 0);
    cudaStreamWaitEvent(s2, evFork, 0);

    k_scan1   <<<NB, 256, 0, s2>>>();
    k_scan2   <<<1, 512, 0, s2>>>();
    k_scan3   <<<NB, 256, 0, s2>>>();
    k_scatter <<<(NE + 255) / 256, 256, 0, s2>>>(src, dst, eattr);
    cudaEventRecord(evJoin, s2);

    k_wprep    <<<48, 256>>>(w1, w2, v);
    k_node_mma <<<NT, 512, SMEM_NODE>>>(feat, w2);

    cudaStreamWaitEvent(0, evJoin, 0);
    k_fused <<<NT, 1024, SMEM_FUSED>>>(bond, out);
}

// round 10
// speedup vs baseline: 1.1883x; 1.0210x over previous
#include <cuda_runtime.h>
#include <cuda_bf16.h>
#include <cstdint>

#define NN 100000
#define NE 800000
#define F  128
#define NT 782              // ceil(NN/128) node tiles
#define NB 391              // ceil(NN/256) scan blocks
#define LDA 136             // smem row stride in bf16 elements
#define REG_BYTES (128 * LDA * 2)   // 34816

// fused kernel smem layout (bytes)
#define AS_OFF 0
#define AH_OFF 65536
#define AL_OFF (AH_OFF + REG_BYTES)
#define BH_OFF (AL_OFF + REG_BYTES)
#define BL_OFF (BH_OFF + REG_BYTES)
#define SMEM_FUSED (BL_OFF + REG_BYTES)   // 204800
// tables overlay the B region during phase 1 (v tiles loaded after gather)
#define EW_OFF  BH_OFF                    // 16384 B  bond table fp32
#define LEW_OFF (BH_OFF + 16384)          // 16384 B  log|ew| fp32
#define SGN_OFF (BH_OFF + 32768)          // 4096  B  ew sign nibbles

// ---------------- scratch ----------------------------------------------------
__device__ int      g_indeg_i [NN];
__device__ int      g_outdeg_i[NN];
__device__ int      g_rowstart[NN];
__device__ int      g_cursor  [NN];
__device__ float    g_rin     [NN];
__device__ int      g_blksum  [512];
__device__ unsigned g_csr     [NE];
__device__ float    g_hsum [(size_t)NN * F];
__device__ float    g_slhp [(size_t)NN * F];     // sign-encoded log|tanh(...)|
__device__ float    g_lew  [32 * F];             // log|bond|
__device__ unsigned g_lewsgn[32 * 32];           // sign nibbles per (type, lane)
__device__ __nv_bfloat16 g_w1h[F * F], g_w1l[F * F];
__device__ __nv_bfloat16 g_w2h[F * F], g_w2l[F * F];
__device__ __nv_bfloat16 g_vh [F * F], g_vl [F * F];

// ---------------- helpers ----------------------------------------------------
__device__ __forceinline__ uint32_t smem_to_u32(const void* p) {
    uint32_t a;
    asm("{ .reg .u64 t; cvta.to.shared.u64 t, %1; cvt.u32.u64 %0, t; }" : "=r"(a) : "l"(p));
    return a;
}

__device__ __forceinline__ void ldsm4(uint32_t& r0, uint32_t& r1, uint32_t& r2, uint32_t& r3,
                                      uint32_t addr) {
    asm volatile("ldmatrix.sync.aligned.m8n8.x4.shared.b16 {%0,%1,%2,%3}, [%4];"
                 : "=r"(r0), "=r"(r1), "=r"(r2), "=r"(r3) : "r"(addr));
}

__device__ __forceinline__ void mma_bf16(float* c, const uint32_t* a, const uint32_t* b) {
    asm volatile("mma.sync.aligned.m16n8k16.row.col.f32.bf16.bf16.f32 "
                 "{%0,%1,%2,%3}, {%4,%5,%6,%7}, {%8,%9}, {%0,%1,%2,%3};"
                 : "+f"(c[0]), "+f"(c[1]), "+f"(c[2]), "+f"(c[3])
                 : "r"(a[0]), "r"(a[1]), "r"(a[2]), "r"(a[3]), "r"(b[0]), "r"(b[1]));
}

__device__ __forceinline__ void split4(float4 x, uint2& H, uint2& L) {
    float xs[4] = {x.x, x.y, x.z, x.w};
    unsigned short h[4], l[4];
#pragma unroll
    for (int j = 0; j < 4; j++) {
        __nv_bfloat16 bh = __float2bfloat16(xs[j]);
        float r = xs[j] - __bfloat162float(bh);
        __nv_bfloat16 bl = __float2bfloat16(r);
        h[j] = __bfloat16_as_ushort(bh);
        l[j] = __bfloat16_as_ushort(bl);
    }
    H = make_uint2((uint32_t)h[0] | ((uint32_t)h[1] << 16),
                   (uint32_t)h[2] | ((uint32_t)h[3] << 16));
    L = make_uint2((uint32_t)l[0] | ((uint32_t)l[1] << 16),
                   (uint32_t)l[2] | ((uint32_t)l[3] << 16));
}

// ---------------- CSR build --------------------------------------------------
__global__ void k_count(const int* __restrict__ src, const int* __restrict__ dst) {
    int e = blockIdx.x * blockDim.x + threadIdx.x;
    if (e < NE) {
        atomicAdd(&g_indeg_i [dst[e]], 1);
        atomicAdd(&g_outdeg_i[src[e]], 1);
    }
}

__global__ void k_scan1() {
    __shared__ int swarp[8];
    int t = threadIdx.x, b = blockIdx.x;
    int i = b * 256 + t;
    int v = (i < NN) ? g_indeg_i[i] : 0;
    int x = v;
    int lane = t & 31, w = t >> 5;
#pragma unroll
    for (int o = 1; o < 32; o <<= 1) {
        int y = __shfl_up_sync(0xffffffffu, x, o);
        if (lane >= o) x += y;
    }
    if (lane == 31) swarp[w] = x;
    __syncthreads();
    if (w == 0) {
        int s = (lane < 8) ? swarp[lane] : 0;
#pragma unroll
        for (int o = 1; o < 8; o <<= 1) {
            int y = __shfl_up_sync(0xffffffffu, s, o);
            if (lane >= o) s += y;
        }
        if (lane < 8) swarp[lane] = s;
    }
    __syncthreads();
    int off = (w > 0) ? swarp[w - 1] : 0;
    if (i < NN) g_rowstart[i] = x - v + off;
    if (t == 255) g_blksum[b] = x + off;
}

__global__ void k_scan2() {
    __shared__ int swarp[16];
    int t = threadIdx.x;
    int v = (t < NB) ? g_blksum[t] : 0;
    int x = v;
    int lane = t & 31, w = t >> 5;
#pragma unroll
    for (int o = 1; o < 32; o <<= 1) {
        int y = __shfl_up_sync(0xffffffffu, x, o);
        if (lane >= o) x += y;
    }
    if (lane == 31) swarp[w] = x;
    __syncthreads();
    if (w == 0) {
        int s = (lane < 16) ? swarp[lane] : 0;
#pragma unroll
        for (int o = 1; o < 16; o <<= 1) {
            int y = __shfl_up_sync(0xffffffffu, s, o);
            if (lane >= o) s += y;
        }
        if (lane < 16) swarp[lane] = s;
    }
    __syncthreads();
    int off = (w > 0) ? swarp[w - 1] : 0;
    if (t < NB) g_blksum[t] = x - v + off;
}

__global__ void k_scan3() {
    int i = blockIdx.x * 256 + threadIdx.x;
    if (i < NN) {
        int r = g_rowstart[i] + g_blksum[blockIdx.x];
        g_rowstart[i] = r;
        g_cursor[i]   = r;
        g_rin[i]      = rsqrtf(fmaxf((float)g_indeg_i[i], 1.0f));
    }
}

__global__ void k_scatter(const int* __restrict__ src, const int* __restrict__ dst,
                          const int* __restrict__ eattr) {
    int e = blockIdx.x * blockDim.x + threadIdx.x;
    if (e < NE) {
        int d = dst[e];
        int pos = atomicAdd(&g_cursor[d], 1);
        g_csr[pos] = (unsigned)src[e] | ((unsigned)eattr[e] << 17);
    }
}

// ---------------- weights -> bf16 hi/lo B^T images --------------------------
__global__ void k_wprep(const float* __restrict__ w1, const float* __restrict__ w2,
                        const float* __restrict__ v) {
    int idx = blockIdx.x * 256 + threadIdx.x;
    if (idx >= 12288) return;
    int mat = idx >> 12;
    int rem = idx & 4095;
    int o  = rem >> 5;
    int k0 = (rem & 31) * 4;
    const float* src = (mat == 0) ? w1 : (mat == 1) ? w2 : v;
    __nv_bfloat16* hi = (mat == 0) ? g_w1h : (mat == 1) ? g_w2h : g_vh;
    __nv_bfloat16* lo = (mat == 0) ? g_w1l : (mat == 1) ? g_w2l : g_vl;
    float4 x;
    x.x = src[(size_t)(k0 + 0) * F + o];
    x.y = src[(size_t)(k0 + 1) * F + o];
    x.z = src[(size_t)(k0 + 2) * F + o];
    x.w = src[(size_t)(k0 + 3) * F + o];
    uint2 H, L; split4(x, H, L);
    *reinterpret_cast<uint2*>(&hi[o * F + k0]) = H;
    *reinterpret_cast<uint2*>(&lo[o * F + k0]) = L;
}

// ---------------- bond -> log|ew| + sign nibbles ----------------------------
__global__ void k_eprep(const float* __restrict__ bond) {
    int t = blockIdx.x;          // 32 bond types
    int g = threadIdx.x;         // 32 lanes
    float4 e = *reinterpret_cast<const float4*>(&bond[t * F + g * 4]);
    float4 le;
    le.x = __logf(fabsf(e.x));
    le.y = __logf(fabsf(e.y));
    le.z = __logf(fabsf(e.z));
    le.w = __logf(fabsf(e.w));
    *reinterpret_cast<float4*>(&g_lew[t * F + g * 4]) = le;
    unsigned sgn =  (__float_as_uint(e.x) >> 31)
                 | ((__float_as_uint(e.y) >> 31) << 1)
                 | ((__float_as_uint(e.z) >> 31) << 2)
                 | ((__float_as_uint(e.w) >> 31) << 3);
    g_lewsgn[t * 32 + g] = sgn;
}

// ---------------- fused dual node GEMM via mma.sync (512 threads) -----------
__global__ __launch_bounds__(512, 1) void k_node_mma(const float* __restrict__ feat,
                                                     const float* __restrict__ w2full) {
    extern __shared__ __align__(16) unsigned char smem[];
    __nv_bfloat16* Ah = (__nv_bfloat16*)smem;
    __nv_bfloat16* Al = Ah + 128 * LDA;
    __nv_bfloat16* Bw[4];
    Bw[0] = Al    + 128 * LDA;
    Bw[1] = Bw[0] + 128 * LDA;
    Bw[2] = Bw[1] + 128 * LDA;
    Bw[3] = Bw[2] + 128 * LDA;

    const int tid = threadIdx.x, lane = tid & 31, wid = tid >> 5;
    const int bid = blockIdx.x;

    {
        int r = tid >> 2, hf = tid & 3;
        int n = bid * 128 + r;
        float s = 0.0f;
        if (n < NN) s = rsqrtf(fmaxf((float)g_outdeg_i[n], 1.0f));
#pragma unroll
        for (int q = 0; q < 8; q++) {
            int k0 = hf * 32 + q * 4;
            float4 x = make_float4(0.f, 0.f, 0.f, 0.f);
            if (n < NN) {
                x = *reinterpret_cast<const float4*>(&feat[(size_t)n * F + k0]);
                x.x *= s; x.y *= s; x.z *= s; x.w *= s;
            }
            uint2 H, L; split4(x, H, L);
            *reinterpret_cast<uint2*>(&Ah[r * LDA + k0]) = H;
            *reinterpret_cast<uint2*>(&Al[r * LDA + k0]) = L;
        }
    }
    {
        const uint4* s0 = (const uint4*)g_w1h; const uint4* s1 = (const uint4*)g_w1l;
        const uint4* s2 = (const uint4*)g_w2h; const uint4* s3 = (const uint4*)g_w2l;
#pragma unroll
        for (int i = 0; i < 4; i++) {
            int idx = tid + i * 512;
            int row = idx >> 4, col = idx & 15;
            ((uint4*)Bw[0])[row * 17 + col] = s0[idx];
            ((uint4*)Bw[1])[row * 17 + col] = s1[idx];
            ((uint4*)Bw[2])[row * 17 + col] = s2[idx];
            ((uint4*)Bw[3])[row * 17 + col] = s3[idx];
        }
    }
    __syncthreads();

    const int warp_m = wid & 1, warp_n = wid >> 1;
    const uint32_t sbase = smem_to_u32(smem);
    const uint32_t aAh = sbase, aAl = sbase + REG_BYTES;
    const int nl0 = (warp_n & 3) * 32;

    float c[4][4][4];
#pragma unroll
    for (int i = 0; i < 4; i++)
#pragma unroll
        for (int j = 0; j < 4; j++)
#pragma unroll
            for (int q = 0; q < 4; q++) c[i][j][q] = 0.f;

#pragma unroll 1
    for (int p = 0; p < 3; p++) {
        uint32_t Abase = (p == 2) ? aAl : aAh;
        uint32_t Bbase = sbase + (uint32_t)(2 + 2 * (warp_n >> 2) + (p == 1)) * REG_BYTES;
#pragma unroll
        for (int ks = 0; ks < 8; ks++) {
            int k0 = ks * 16;
            uint32_t a[4][4];
#pragma unroll
            for (int i = 0; i < 4; i++) {
                int row = warp_m * 64 + i * 16 + (lane & 15);
                ldsm4(a[i][0], a[i][1], a[i][2], a[i][3],
                      Abase + (uint32_t)(row * LDA + k0 + ((lane >> 4) << 3)) * 2);
            }
            uint32_t b[4][2];
#pragma unroll
            for (int jj = 0; jj < 2; jj++) {
                int o = nl0 + jj * 16 + (lane & 7) + ((lane >> 4) << 3);
                uint32_t r0, r1, r2, r3;
                ldsm4(r0, r1, r2, r3,
                      Bbase + (uint32_t)(o * LDA + k0 + (((lane >> 3) & 1) << 3)) * 2);
                b[jj * 2][0] = r0; b[jj * 2][1] = r1;
                b[jj * 2 + 1][0] = r2; b[jj * 2 + 1][1] = r3;
            }
#pragma unroll
            for (int i = 0; i < 4; i++)
#pragma unroll
                for (int j = 0; j < 4; j++)
                    mma_bf16(c[i][j], a[i], b[j]);
        }
    }

    const int colbase = warp_n * 32;
#pragma unroll
    for (int i = 0; i < 4; i++) {
        int r0 = warp_m * 64 + i * 16 + (lane >> 2);
        int n0 = bid * 128 + r0;
        int n1 = n0 + 8;
#pragma unroll
        for (int j = 0; j < 4; j++) {
            int col = colbase + j * 8 + (lane & 3) * 2;
            if (col < 128) {
                if (n0 < NN)
                    *reinterpret_cast<float2*>(&g_hsum[(size_t)n0 * F + col]) =
                        make_float2(c[i][j][0], c[i][j][1]);
                if (n1 < NN)
                    *reinterpret_cast<float2*>(&g_hsum[(size_t)n1 * F + col]) =
                        make_float2(c[i][j][2], c[i][j][3]);
            } else {
                int c2 = col - 128;
                float2 bias = *reinterpret_cast<const float2*>(&w2full[(size_t)128 * F + c2]);
                // hp = tanh(acc+bias); store sign-encoded biased log:
                // s = sign(hp) * (log|hp| - 1)  with log|hp| <= 0 -> |s| >= 1
                if (n0 < NN) {
                    float t0 = tanhf(c[i][j][0] + bias.x);
                    float t1 = tanhf(c[i][j][1] + bias.y);
                    float l0 = __logf(fabsf(t0)) - 1.0f;
                    float l1 = __logf(fabsf(t1)) - 1.0f;
                    float s0 = (t0 < 0.f) ? -l0 : l0;
                    float s1 = (t1 < 0.f) ? -l1 : l1;
                    *reinterpret_cast<float2*>(&g_slhp[(size_t)n0 * F + c2]) =
                        make_float2(s0, s1);
                }
                if (n1 < NN) {
                    float t0 = tanhf(c[i][j][2] + bias.x);
                    float t1 = tanhf(c[i][j][3] + bias.y);
                    float l0 = __logf(fabsf(t0)) - 1.0f;
                    float l1 = __logf(fabsf(t1)) - 1.0f;
                    float s0 = (t0 < 0.f) ? -l0 : l0;
                    float s1 = (t1 < 0.f) ? -l1 : l1;
                    *reinterpret_cast<float2*>(&g_slhp[(size_t)n1 * F + c2]) =
                        make_float2(s0, s1);
                }
            }
        }
    }
}

// ---------------- fused gather + final GEMM (1024 threads) -------------------
__global__ __launch_bounds__(1024, 1) void k_fused(const float* __restrict__ bond,
                                                   float* __restrict__ out) {
    extern __shared__ __align__(16) unsigned char smem[];
    float*        As  = (float*)(smem + AS_OFF);
    __nv_bfloat16* Ah = (__nv_bfloat16*)(smem + AH_OFF);
    __nv_bfloat16* Al = (__nv_bfloat16*)(smem + AL_OFF);
    float*        ewS  = (float*)(smem + EW_OFF);
    float*        lewS = (float*)(smem + LEW_OFF);
    unsigned*     sgnS = (unsigned*)(smem + SGN_OFF);

    const int tid = threadIdx.x, lane = tid & 31, wid = tid >> 5;
    const int bid = blockIdx.x;
    const int g = lane;

    // stage bond / log-bond / sign tables into smem (B region, phase-1 only)
    {
#pragma unroll
        for (int i = 0; i < 4; i++) {
            int idx = tid + i * 1024;   // 4096 floats
            ewS[idx]  = bond[idx];
            lewS[idx] = g_lew[idx];
        }
        if (tid < 1024) sgnS[tid] = g_lewsgn[tid];
    }
    __syncthreads();

    const float4* hs4 = (const float4*)g_hsum;
    const float4* sl4 = (const float4*)g_slhp;
    const float4* ew4 = (const float4*)ewS;
    const float4* lw4 = (const float4*)lewS;

    // Phase 1: gather. 32 warps, 4 nodes each
#pragma unroll 1
    for (int q = 0; q < 4; q++) {
        int r = wid * 4 + q;
        int n = bid * 128 + r;

        float4 as = make_float4(0.f, 0.f, 0.f, 0.f);
        float4 al = make_float4(0.f, 0.f, 0.f, 0.f);
        unsigned sg = 0;
        int deg = 0;

        if (n < NN) {
            int base = g_rowstart[n];
            deg = g_indeg_i[n];
            int i = 0;
            for (; i + 2 <= deg; i += 2) {
                unsigned c0 = __ldg(&g_csr[base + i]);
                unsigned c1 = __ldg(&g_csr[base + i + 1]);
                int s0 = c0 & 0x1FFFF, a0 = c0 >> 17;
                int s1 = c1 & 0x1FFFF, a1 = c1 >> 17;
                float4 h0 = __ldg(hs4 + (size_t)s0 * 32 + g);
                float4 h1 = __ldg(hs4 + (size_t)s1 * 32 + g);
                float4 x0 = __ldg(sl4 + (size_t)s0 * 32 + g);
                float4 x1 = __ldg(sl4 + (size_t)s1 * 32 + g);
                float4 e0 = ew4[a0 * 32 + g];
                float4 e1 = ew4[a1 * 32 + g];
                float4 w0 = lw4[a0 * 32 + g];
                float4 w1 = lw4[a1 * 32 + g];
                unsigned es = sgnS[a0 * 32 + g] ^ sgnS[a1 * 32 + g];

                as.x += h0.x*e0.x + h1.x*e1.x;
                as.y += h0.y*e0.y + h1.y*e1.y;
                as.z += h0.z*e0.z + h1.z*e1.z;
                as.w += h0.w*e0.w + h1.w*e1.w;

                al.x += (w0.x - fabsf(x0.x)) + (w1.x - fabsf(x1.x));
                al.y += (w0.y - fabsf(x0.y)) + (w1.y - fabsf(x1.y));
                al.z += (w0.z - fabsf(x0.z)) + (w1.z - fabsf(x1.z));
                al.w += (w0.w - fabsf(x0.w)) + (w1.w - fabsf(x1.w));

                unsigned b0 =  ((~__float_as_uint(x0.x)) >> 31)
                            | (((~__float_as_uint(x0.y)) >> 31) << 1)
                            | (((~__float_as_uint(x0.z)) >> 31) << 2)
                            | (((~__float_as_uint(x0.w)) >> 31) << 3);
                unsigned b1 =  ((~__float_as_uint(x1.x)) >> 31)
                            | (((~__float_as_uint(x1.y)) >> 31) << 1)
                            | (((~__float_as_uint(x1.z)) >> 31) << 2)
                            | (((~__float_as_uint(x1.w)) >> 31) << 3);
                sg ^= es ^ b0 ^ b1;
            }
            if (i < deg) {
                unsigned c0 = __ldg(&g_csr[base + i]);
                int s0 = c0 & 0x1FFFF, a0 = c0 >> 17;
                float4 h0 = __ldg(hs4 + (size_t)s0 * 32 + g);
                float4 x0 = __ldg(sl4 + (size_t)s0 * 32 + g);
                float4 e0 = ew4[a0 * 32 + g];
                float4 w0 = lw4[a0 * 32 + g];
                unsigned es = sgnS[a0 * 32 + g];

                as.x += h0.x*e0.x; as.y += h0.y*e0.y;
                as.z += h0.z*e0.z; as.w += h0.w*e0.w;
                al.x += w0.x - fabsf(x0.x);
                al.y += w0.y - fabsf(x0.y);
                al.z += w0.z - fabsf(x0.z);
                al.w += w0.w - fabsf(x0.w);
                unsigned b0 =  ((~__float_as_uint(x0.x)) >> 31)
                            | (((~__float_as_uint(x0.y)) >> 31) << 1)
                            | (((~__float_as_uint(x0.z)) >> 31) << 2)
                            | (((~__float_as_uint(x0.w)) >> 31) << 3);
                sg ^= es ^ b0;
            }
        }

        *reinterpret_cast<float4*>(&As[r * 128 + g * 4]) = as;

        // hp = sign * exp(al + deg)   (undo the -1 bias per factor)
        float4 hp = make_float4(0.f, 0.f, 0.f, 0.f);
        if (n < NN) {
            float dc = (float)deg;
            hp.x = __expf(al.x + dc); if (sg & 1u) hp.x = -hp.x;
            hp.y = __expf(al.y + dc); if (sg & 2u) hp.y = -hp.y;
            hp.z = __expf(al.z + dc); if (sg & 4u) hp.z = -hp.z;
            hp.w = __expf(al.w + dc); if (sg & 8u) hp.w = -hp.w;
        }
        uint2 H, L; split4(hp, H, L);
        *reinterpret_cast<uint2*>(&Ah[r * LDA + g * 4]) = H;
        *reinterpret_cast<uint2*>(&Al[r * LDA + g * 4]) = L;
    }
    __syncthreads();

    // load v tiles into B region (overwrites tables; gather is done)
    {
        const uint4* s0 = (const uint4*)g_vh;
        const uint4* s1 = (const uint4*)g_vl;
        uint4* d0 = (uint4*)(smem + BH_OFF);
        uint4* d1 = (uint4*)(smem + BL_OFF);
#pragma unroll
        for (int i = 0; i < 2; i++) {
            int idx = tid + i * 1024;
            int row = idx >> 4, col = idx & 15;
            d0[row * 17 + col] = s0[idx];
            d1[row * 17 + col] = s1[idx];
        }
    }
    __syncthreads();

    // Phase 2: MMA 128x128, 32 warps (4 x 8 of 32x16 tiles)
    const int warp_m = wid & 3, warp_n = wid >> 2;
    const uint32_t sbase = smem_to_u32(smem);
    const int nl0 = warp_n * 16;

    float c[2][2][4];
#pragma unroll
    for (int i = 0; i < 2; i++)
#pragma unroll
        for (int j = 0; j < 2; j++)
#pragma unroll
            for (int q = 0; q < 4; q++) c[i][j][q] = 0.f;

#pragma unroll 1
    for (int p = 0; p < 3; p++) {
        uint32_t Abase = sbase + ((p == 2) ? AL_OFF : AH_OFF);
        uint32_t Bbase = sbase + ((p == 1) ? BL_OFF : BH_OFF);
#pragma unroll
        for (int ks = 0; ks < 8; ks++) {
            int k0 = ks * 16;
            uint32_t a[2][4];
#pragma unroll
            for (int i = 0; i < 2; i++) {
                int row = warp_m * 32 + i * 16 + (lane & 15);
                ldsm4(a[i][0], a[i][1], a[i][2], a[i][3],
                      Abase + (uint32_t)(row * LDA + k0 + ((lane >> 4) << 3)) * 2);
            }
            uint32_t b[2][2];
            {
                int o = nl0 + (lane & 7) + ((lane >> 4) << 3);
                uint32_t r0, r1, r2, r3;
                ldsm4(r0, r1, r2, r3,
                      Bbase + (uint32_t)(o * LDA + k0 + (((lane >> 3) & 1) << 3)) * 2);
                b[0][0] = r0; b[0][1] = r1;
                b[1][0] = r2; b[1][1] = r3;
            }
#pragma unroll
            for (int i = 0; i < 2; i++)
#pragma unroll
                for (int j = 0; j < 2; j++)
                    mma_bf16(c[i][j], a[i], b[j]);
        }
    }

    // epilogue: out = (As + C) * rin
#pragma unroll
    for (int i = 0; i < 2; i++) {
        int r0 = warp_m * 32 + i * 16 + (lane >> 2);
        int r1 = r0 + 8;
        int n0 = bid * 128 + r0;
        int n1 = n0 + 8;
        float rin0 = (n0 < NN) ? g_rin[n0] : 0.f;
        float rin1 = (n1 < NN) ? g_rin[n1] : 0.f;
#pragma unroll
        for (int j = 0; j < 2; j++) {
            int col = nl0 + j * 8 + (lane & 3) * 2;
            if (n0 < NN) {
                float2 prev = *reinterpret_cast<float2*>(&As[r0 * 128 + col]);
                *reinterpret_cast<float2*>(&out[(size_t)n0 * F + col]) =
                    make_float2((prev.x + c[i][j][0]) * rin0,
                                (prev.y + c[i][j][1]) * rin0);
            }
            if (n1 < NN) {
                float2 prev = *reinterpret_cast<float2*>(&As[r1 * 128 + col]);
                *reinterpret_cast<float2*>(&out[(size_t)n1 * F + col]) =
                    make_float2((prev.x + c[i][j][2]) * rin1,
                                (prev.y + c[i][j][3]) * rin1);
            }
        }
    }
}

// ---------------- launcher ---------------------------------------------------
#define SMEM_NODE (6 * REG_BYTES)

extern "C" void kernel_launch(void* const* d_in, const int* in_sizes, int n_in,
                              void* d_out, int out_size) {
    const float* feat  = (const float*)d_in[0];
    const int*   src   = (const int*)  d_in[1];
    const int*   dst   = (const int*)  d_in[2];
    const int*   eattr = (const int*)  d_in[3];
    const float* w1    = (const float*)d_in[4];
    const float* w2    = (const float*)d_in[5];
    const float* v     = (const float*)d_in[6];
    const float* bond  = (const float*)d_in[7];
    float* out = (float*)d_out;

    static cudaStream_t s2 = nullptr;
    static cudaEvent_t evFork = nullptr, evJoin = nullptr;
    if (s2 == nullptr) {
        cudaStreamCreateWithFlags(&s2, cudaStreamNonBlocking);
        cudaEventCreateWithFlags(&evFork, cudaEventDisableTiming);
        cudaEventCreateWithFlags(&evJoin, cudaEventDisableTiming);
        cudaFuncSetAttribute(k_node_mma, cudaFuncAttributeMaxDynamicSharedMemorySize, SMEM_NODE);
        cudaFuncSetAttribute(k_fused,    cudaFuncAttributeMaxDynamicSharedMemorySize, SMEM_FUSED);
    }

    void *p_id, *p_od;
    cudaGetSymbolAddress(&p_id, g_indeg_i);
    cudaGetSymbolAddress(&p_od, g_outdeg_i);
    cudaMemsetAsync(p_id, 0, NN * sizeof(int));
    cudaMemsetAsync(p_od, 0, NN * sizeof(int));

    k_count <<<(NE + 255) / 256, 256>>>(src, dst);

    cudaEventRecord(evFork, 0);
    cudaStreamWaitEvent(s2, evFork, 0);

    k_scan1   <<<NB, 256, 0, s2>>>();
    k_scan2   <<<1, 512, 0, s2>>>();
    k_scan3   <<<NB, 256, 0, s2>>>();
    k_scatter <<<(NE + 255) / 256, 256, 0, s2>>>(src, dst, eattr);
    cudaEventRecord(evJoin, s2);

    k_wprep    <<<48, 256>>>(w1, w2, v);
    k_eprep    <<<32, 32>>>(bond);
    k_node_mma <<<NT, 512, SMEM_NODE>>>(feat, w2);

    cudaStreamWaitEvent(0, evJoin, 0);
    k_fused <<<NT, 1024, SMEM_FUSED>>>(bond, out);
}

// round 11
// speedup vs baseline: 1.2670x; 1.0662x over previous
#include <cuda_runtime.h>
#include <cuda_bf16.h>
#include <cstdint>

#define NN 100000
#define NE 800000
#define F  128
#define NT 782              // ceil(NN/128) node tiles
#define NB 391              // ceil(NN/256) scan blocks
#define LDA 136             // smem row stride in bf16 elements
#define REG_BYTES (128 * LDA * 2)   // 34816
#define PKF 192             // pack row stride in floats (512B hs + 256B slhp)

// fused kernel smem layout (bytes)
#define AS_OFF 0
#define AH_OFF 65536
#define AL_OFF (AH_OFF + REG_BYTES)
#define BH_OFF (AL_OFF + REG_BYTES)
#define BL_OFF (BH_OFF + REG_BYTES)
#define SMEM_FUSED (BL_OFF + REG_BYTES)   // 204800
// tables overlay the B region during phase 1
#define EW_OFF  BH_OFF
#define LEW_OFF (BH_OFF + 16384)
#define SGN_OFF (BH_OFF + 32768)

// ---------------- scratch ----------------------------------------------------
__device__ int      g_indeg_i [NN];
__device__ int      g_outdeg_i[NN];
__device__ int      g_rowstart[NN];
__device__ int      g_cursor  [NN];
__device__ float    g_rin     [NN];
__device__ int      g_blksum  [512];
__device__ unsigned g_csr     [NE];
__device__ float    g_pack [(size_t)NN * PKF];   // per node: 128 f32 hs | 128 bf16 slhp
__device__ float    g_lew  [32 * F];
__device__ unsigned g_lewsgn[32 * 32];
__device__ __nv_bfloat16 g_w1h[F * F], g_w1l[F * F];
__device__ __nv_bfloat16 g_w2h[F * F], g_w2l[F * F];
__device__ __nv_bfloat16 g_vh [F * F], g_vl [F * F];

// ---------------- helpers ----------------------------------------------------
__device__ __forceinline__ uint32_t smem_to_u32(const void* p) {
    uint32_t a;
    asm("{ .reg .u64 t; cvta.to.shared.u64 t, %1; cvt.u32.u64 %0, t; }" : "=r"(a) : "l"(p));
    return a;
}

__device__ __forceinline__ void ldsm4(uint32_t& r0, uint32_t& r1, uint32_t& r2, uint32_t& r3,
                                      uint32_t addr) {
    asm volatile("ldmatrix.sync.aligned.m8n8.x4.shared.b16 {%0,%1,%2,%3}, [%4];"
                 : "=r"(r0), "=r"(r1), "=r"(r2), "=r"(r3) : "r"(addr));
}

__device__ __forceinline__ void mma_bf16(float* c, const uint32_t* a, const uint32_t* b) {
    asm volatile("mma.sync.aligned.m16n8k16.row.col.f32.bf16.bf16.f32 "
                 "{%0,%1,%2,%3}, {%4,%5,%6,%7}, {%8,%9}, {%0,%1,%2,%3};"
                 : "+f"(c[0]), "+f"(c[1]), "+f"(c[2]), "+f"(c[3])
                 : "r"(a[0]), "r"(a[1]), "r"(a[2]), "r"(a[3]), "r"(b[0]), "r"(b[1]));
}

__device__ __forceinline__ void split4(float4 x, uint2& H, uint2& L) {
    float xs[4] = {x.x, x.y, x.z, x.w};
    unsigned short h[4], l[4];
#pragma unroll
    for (int j = 0; j < 4; j++) {
        __nv_bfloat16 bh = __float2bfloat16(xs[j]);
        float r = xs[j] - __bfloat162float(bh);
        __nv_bfloat16 bl = __float2bfloat16(r);
        h[j] = __bfloat16_as_ushort(bh);
        l[j] = __bfloat16_as_ushort(bl);
    }
    H = make_uint2((uint32_t)h[0] | ((uint32_t)h[1] << 16),
                   (uint32_t)h[2] | ((uint32_t)h[3] << 16));
    L = make_uint2((uint32_t)l[0] | ((uint32_t)l[1] << 16),
                   (uint32_t)l[2] | ((uint32_t)l[3] << 16));
}

// ---------------- CSR build --------------------------------------------------
__global__ void k_count(const int* __restrict__ src, const int* __restrict__ dst) {
    int e = blockIdx.x * blockDim.x + threadIdx.x;
    if (e < NE) {
        atomicAdd(&g_indeg_i [dst[e]], 1);
        atomicAdd(&g_outdeg_i[src[e]], 1);
    }
}

__global__ void k_scan1() {
    __shared__ int swarp[8];
    int t = threadIdx.x, b = blockIdx.x;
    int i = b * 256 + t;
    int v = (i < NN) ? g_indeg_i[i] : 0;
    int x = v;
    int lane = t & 31, w = t >> 5;
#pragma unroll
    for (int o = 1; o < 32; o <<= 1) {
        int y = __shfl_up_sync(0xffffffffu, x, o);
        if (lane >= o) x += y;
    }
    if (lane == 31) swarp[w] = x;
    __syncthreads();
    if (w == 0) {
        int s = (lane < 8) ? swarp[lane] : 0;
#pragma unroll
        for (int o = 1; o < 8; o <<= 1) {
            int y = __shfl_up_sync(0xffffffffu, s, o);
            if (lane >= o) s += y;
        }
        if (lane < 8) swarp[lane] = s;
    }
    __syncthreads();
    int off = (w > 0) ? swarp[w - 1] : 0;
    if (i < NN) g_rowstart[i] = x - v + off;
    if (t == 255) g_blksum[b] = x + off;
}

__global__ void k_scan2() {
    __shared__ int swarp[16];
    int t = threadIdx.x;
    int v = (t < NB) ? g_blksum[t] : 0;
    int x = v;
    int lane = t & 31, w = t >> 5;
#pragma unroll
    for (int o = 1; o < 32; o <<= 1) {
        int y = __shfl_up_sync(0xffffffffu, x, o);
        if (lane >= o) x += y;
    }
    if (lane == 31) swarp[w] = x;
    __syncthreads();
    if (w == 0) {
        int s = (lane < 16) ? swarp[lane] : 0;
#pragma unroll
        for (int o = 1; o < 16; o <<= 1) {
            int y = __shfl_up_sync(0xffffffffu, s, o);
            if (lane >= o) s += y;
        }
        if (lane < 16) swarp[lane] = s;
    }
    __syncthreads();
    int off = (w > 0) ? swarp[w - 1] : 0;
    if (t < NB) g_blksum[t] = x - v + off;
}

__global__ void k_scan3() {
    int i = blockIdx.x * 256 + threadIdx.x;
    if (i < NN) {
        int r = g_rowstart[i] + g_blksum[blockIdx.x];
        g_rowstart[i] = r;
        g_cursor[i]   = r;
        g_rin[i]      = rsqrtf(fmaxf((float)g_indeg_i[i], 1.0f));
    }
}

__global__ void k_scatter(const int* __restrict__ src, const int* __restrict__ dst,
                          const int* __restrict__ eattr) {
    int e = blockIdx.x * blockDim.x + threadIdx.x;
    if (e < NE) {
        int d = dst[e];
        int pos = atomicAdd(&g_cursor[d], 1);
        g_csr[pos] = (unsigned)src[e] | ((unsigned)eattr[e] << 17);
    }
}

// ---------------- weights -> bf16 hi/lo B^T images --------------------------
__global__ void k_wprep(const float* __restrict__ w1, const float* __restrict__ w2,
                        const float* __restrict__ v) {
    int idx = blockIdx.x * 256 + threadIdx.x;
    if (idx >= 12288) return;
    int mat = idx >> 12;
    int rem = idx & 4095;
    int o  = rem >> 5;
    int k0 = (rem & 31) * 4;
    const float* src = (mat == 0) ? w1 : (mat == 1) ? w2 : v;
    __nv_bfloat16* hi = (mat == 0) ? g_w1h : (mat == 1) ? g_w2h : g_vh;
    __nv_bfloat16* lo = (mat == 0) ? g_w1l : (mat == 1) ? g_w2l : g_vl;
    float4 x;
    x.x = src[(size_t)(k0 + 0) * F + o];
    x.y = src[(size_t)(k0 + 1) * F + o];
    x.z = src[(size_t)(k0 + 2) * F + o];
    x.w = src[(size_t)(k0 + 3) * F + o];
    uint2 H, L; split4(x, H, L);
    *reinterpret_cast<uint2*>(&hi[o * F + k0]) = H;
    *reinterpret_cast<uint2*>(&lo[o * F + k0]) = L;
}

// ---------------- bond -> log|ew| + sign nibbles ----------------------------
__global__ void k_eprep(const float* __restrict__ bond) {
    int t = blockIdx.x;
    int g = threadIdx.x;
    float4 e = *reinterpret_cast<const float4*>(&bond[t * F + g * 4]);
    float4 le;
    le.x = __logf(fabsf(e.x));
    le.y = __logf(fabsf(e.y));
    le.z = __logf(fabsf(e.z));
    le.w = __logf(fabsf(e.w));
    *reinterpret_cast<float4*>(&g_lew[t * F + g * 4]) = le;
    unsigned sgn =  (__float_as_uint(e.x) >> 31)
                 | ((__float_as_uint(e.y) >> 31) << 1)
                 | ((__float_as_uint(e.z) >> 31) << 2)
                 | ((__float_as_uint(e.w) >> 31) << 3);
    g_lewsgn[t * 32 + g] = sgn;
}

// ---------------- fused dual node GEMM via mma.sync (512 threads) -----------
__global__ __launch_bounds__(512, 1) void k_node_mma(const float* __restrict__ feat,
                                                     const float* __restrict__ w2full) {
    extern __shared__ __align__(16) unsigned char smem[];
    __nv_bfloat16* Ah = (__nv_bfloat16*)smem;
    __nv_bfloat16* Al = Ah + 128 * LDA;
    __nv_bfloat16* Bw[4];
    Bw[0] = Al    + 128 * LDA;
    Bw[1] = Bw[0] + 128 * LDA;
    Bw[2] = Bw[1] + 128 * LDA;
    Bw[3] = Bw[2] + 128 * LDA;

    const int tid = threadIdx.x, lane = tid & 31, wid = tid >> 5;
    const int bid = blockIdx.x;

    {
        int r = tid >> 2, hf = tid & 3;
        int n = bid * 128 + r;
        float s = 0.0f;
        if (n < NN) s = rsqrtf(fmaxf((float)g_outdeg_i[n], 1.0f));
#pragma unroll
        for (int q = 0; q < 8; q++) {
            int k0 = hf * 32 + q * 4;
            float4 x = make_float4(0.f, 0.f, 0.f, 0.f);
            if (n < NN) {
                x = *reinterpret_cast<const float4*>(&feat[(size_t)n * F + k0]);
                x.x *= s; x.y *= s; x.z *= s; x.w *= s;
            }
            uint2 H, L; split4(x, H, L);
            *reinterpret_cast<uint2*>(&Ah[r * LDA + k0]) = H;
            *reinterpret_cast<uint2*>(&Al[r * LDA + k0]) = L;
        }
    }
    {
        const uint4* s0 = (const uint4*)g_w1h; const uint4* s1 = (const uint4*)g_w1l;
        const uint4* s2 = (const uint4*)g_w2h; const uint4* s3 = (const uint4*)g_w2l;
#pragma unroll
        for (int i = 0; i < 4; i++) {
            int idx = tid + i * 512;
            int row = idx >> 4, col = idx & 15;
            ((uint4*)Bw[0])[row * 17 + col] = s0[idx];
            ((uint4*)Bw[1])[row * 17 + col] = s1[idx];
            ((uint4*)Bw[2])[row * 17 + col] = s2[idx];
            ((uint4*)Bw[3])[row * 17 + col] = s3[idx];
        }
    }
    __syncthreads();

    const int warp_m = wid & 1, warp_n = wid >> 1;
    const uint32_t sbase = smem_to_u32(smem);
    const uint32_t aAh = sbase, aAl = sbase + REG_BYTES;
    const int nl0 = (warp_n & 3) * 32;

    float c[4][4][4];
#pragma unroll
    for (int i = 0; i < 4; i++)
#pragma unroll
        for (int j = 0; j < 4; j++)
#pragma unroll
            for (int q = 0; q < 4; q++) c[i][j][q] = 0.f;

#pragma unroll 1
    for (int p = 0; p < 3; p++) {
        uint32_t Abase = (p == 2) ? aAl : aAh;
        uint32_t Bbase = sbase + (uint32_t)(2 + 2 * (warp_n >> 2) + (p == 1)) * REG_BYTES;
#pragma unroll
        for (int ks = 0; ks < 8; ks++) {
            int k0 = ks * 16;
            uint32_t a[4][4];
#pragma unroll
            for (int i = 0; i < 4; i++) {
                int row = warp_m * 64 + i * 16 + (lane & 15);
                ldsm4(a[i][0], a[i][1], a[i][2], a[i][3],
                      Abase + (uint32_t)(row * LDA + k0 + ((lane >> 4) << 3)) * 2);
            }
            uint32_t b[4][2];
#pragma unroll
            for (int jj = 0; jj < 2; jj++) {
                int o = nl0 + jj * 16 + (lane & 7) + ((lane >> 4) << 3);
                uint32_t r0, r1, r2, r3;
                ldsm4(r0, r1, r2, r3,
                      Bbase + (uint32_t)(o * LDA + k0 + (((lane >> 3) & 1) << 3)) * 2);
                b[jj * 2][0] = r0; b[jj * 2][1] = r1;
                b[jj * 2 + 1][0] = r2; b[jj * 2 + 1][1] = r3;
            }
#pragma unroll
            for (int i = 0; i < 4; i++)
#pragma unroll
                for (int j = 0; j < 4; j++)
                    mma_bf16(c[i][j], a[i], b[j]);
        }
    }

    const int colbase = warp_n * 32;
    unsigned* packu = (unsigned*)g_pack;
#pragma unroll
    for (int i = 0; i < 4; i++) {
        int r0 = warp_m * 64 + i * 16 + (lane >> 2);
        int n0 = bid * 128 + r0;
        int n1 = n0 + 8;
#pragma unroll
        for (int j = 0; j < 4; j++) {
            int col = colbase + j * 8 + (lane & 3) * 2;
            if (col < 128) {
                if (n0 < NN)
                    *reinterpret_cast<float2*>(&g_pack[(size_t)n0 * PKF + col]) =
                        make_float2(c[i][j][0], c[i][j][1]);
                if (n1 < NN)
                    *reinterpret_cast<float2*>(&g_pack[(size_t)n1 * PKF + col]) =
                        make_float2(c[i][j][2], c[i][j][3]);
            } else {
                int c2 = col - 128;
                float2 bias = *reinterpret_cast<const float2*>(&w2full[(size_t)128 * F + c2]);
                // s = sign(hp) * (log|hp| - 1), |s| >= 1; stored bf16x2
                if (n0 < NN) {
                    float t0 = tanhf(c[i][j][0] + bias.x);
                    float t1 = tanhf(c[i][j][1] + bias.y);
                    float l0 = __logf(fabsf(t0)) - 1.0f;
                    float l1 = __logf(fabsf(t1)) - 1.0f;
                    float s0 = (t0 < 0.f) ? -l0 : l0;
                    float s1 = (t1 < 0.f) ? -l1 : l1;
                    unsigned pk = (unsigned)__bfloat16_as_ushort(__float2bfloat16(s0))
                                | ((unsigned)__bfloat16_as_ushort(__float2bfloat16(s1)) << 16);
                    packu[(size_t)n0 * PKF + 128 + (c2 >> 1)] = pk;
                }
                if (n1 < NN) {
                    float t0 = tanhf(c[i][j][2] + bias.x);
                    float t1 = tanhf(c[i][j][3] + bias.y);
                    float l0 = __logf(fabsf(t0)) - 1.0f;
                    float l1 = __logf(fabsf(t1)) - 1.0f;
                    float s0 = (t0 < 0.f) ? -l0 : l0;
                    float s1 = (t1 < 0.f) ? -l1 : l1;
                    unsigned pk = (unsigned)__bfloat16_as_ushort(__float2bfloat16(s0))
                                | ((unsigned)__bfloat16_as_ushort(__float2bfloat16(s1)) << 16);
                    packu[(size_t)n1 * PKF + 128 + (c2 >> 1)] = pk;
                }
            }
        }
    }
}

// ---------------- fused gather + final GEMM (1024 threads) -------------------
__global__ __launch_bounds__(1024, 1) void k_fused(const float* __restrict__ bond,
                                                   float* __restrict__ out) {
    extern __shared__ __align__(16) unsigned char smem[];
    float*        As  = (float*)(smem + AS_OFF);
    __nv_bfloat16* Ah = (__nv_bfloat16*)(smem + AH_OFF);
    __nv_bfloat16* Al = (__nv_bfloat16*)(smem + AL_OFF);
    float*        ewS  = (float*)(smem + EW_OFF);
    float*        lewS = (float*)(smem + LEW_OFF);
    unsigned*     sgnS = (unsigned*)(smem + SGN_OFF);

    const int tid = threadIdx.x, lane = tid & 31, wid = tid >> 5;
    const int bid = blockIdx.x;
    const int g = lane;

    {
#pragma unroll
        for (int i = 0; i < 4; i++) {
            int idx = tid + i * 1024;
            ewS[idx]  = bond[idx];
            lewS[idx] = g_lew[idx];
        }
        if (tid < 1024) sgnS[tid] = g_lewsgn[tid];
    }
    __syncthreads();

    const float4* pk4 = (const float4*)g_pack;   // 48 float4 per row
    const uint2*  pk2 = (const uint2*)g_pack;    // 96 uint2 per row; slhp at +64
    const float4* ew4 = (const float4*)ewS;
    const float4* lw4 = (const float4*)lewS;

    // Phase 1: gather. 32 warps, 4 nodes each
#pragma unroll 1
    for (int q = 0; q < 4; q++) {
        int r = wid * 4 + q;
        int n = bid * 128 + r;

        float4 as = make_float4(0.f, 0.f, 0.f, 0.f);
        float4 al = make_float4(0.f, 0.f, 0.f, 0.f);
        unsigned sg = 0;
        int deg = 0;

        if (n < NN) {
            int base = g_rowstart[n];
            deg = g_indeg_i[n];
            int i = 0;
            for (; i + 2 <= deg; i += 2) {
                unsigned c0 = __ldg(&g_csr[base + i]);
                unsigned c1 = __ldg(&g_csr[base + i + 1]);
                int s0 = c0 & 0x1FFFF, a0 = c0 >> 17;
                int s1 = c1 & 0x1FFFF, a1 = c1 >> 17;
                float4 h0 = __ldg(pk4 + (size_t)s0 * 48 + g);
                float4 h1 = __ldg(pk4 + (size_t)s1 * 48 + g);
                uint2  x0 = __ldg(pk2 + (size_t)s0 * 96 + 64 + g);
                uint2  x1 = __ldg(pk2 + (size_t)s1 * 96 + 64 + g);
                float4 e0 = ew4[a0 * 32 + g];
                float4 e1 = ew4[a1 * 32 + g];
                float4 w0 = lw4[a0 * 32 + g];
                float4 w1 = lw4[a1 * 32 + g];
                unsigned es = sgnS[a0 * 32 + g] ^ sgnS[a1 * 32 + g];

                as.x += h0.x*e0.x + h1.x*e1.x;
                as.y += h0.y*e0.y + h1.y*e1.y;
                as.z += h0.z*e0.z + h1.z*e1.z;
                as.w += h0.w*e0.w + h1.w*e1.w;

                float f00 = __uint_as_float((x0.x & 0xffffu) << 16);
                float f01 = __uint_as_float(x0.x & 0xffff0000u);
                float f02 = __uint_as_float((x0.y & 0xffffu) << 16);
                float f03 = __uint_as_float(x0.y & 0xffff0000u);
                float f10 = __uint_as_float((x1.x & 0xffffu) << 16);
                float f11 = __uint_as_float(x1.x & 0xffff0000u);
                float f12 = __uint_as_float((x1.y & 0xffffu) << 16);
                float f13 = __uint_as_float(x1.y & 0xffff0000u);

                al.x += (w0.x - fabsf(f00)) + (w1.x - fabsf(f10));
                al.y += (w0.y - fabsf(f01)) + (w1.y - fabsf(f11));
                al.z += (w0.z - fabsf(f02)) + (w1.z - fabsf(f12));
                al.w += (w0.w - fabsf(f03)) + (w1.w - fabsf(f13));

                // hp sign bit = NOT sign(s)
                unsigned b0 =  ((~(x0.x >> 15)) & 1u)
                            | (((~(x0.x >> 31)) & 1u) << 1)
                            | (((~(x0.y >> 15)) & 1u) << 2)
                            | (((~(x0.y >> 31)) & 1u) << 3);
                unsigned b1 =  ((~(x1.x >> 15)) & 1u)
                            | (((~(x1.x >> 31)) & 1u) << 1)
                            | (((~(x1.y >> 15)) & 1u) << 2)
                            | (((~(x1.y >> 31)) & 1u) << 3);
                sg ^= es ^ b0 ^ b1;
            }
            if (i < deg) {
                unsigned c0 = __ldg(&g_csr[base + i]);
                int s0 = c0 & 0x1FFFF, a0 = c0 >> 17;
                float4 h0 = __ldg(pk4 + (size_t)s0 * 48 + g);
                uint2  x0 = __ldg(pk2 + (size_t)s0 * 96 + 64 + g);
                float4 e0 = ew4[a0 * 32 + g];
                float4 w0 = lw4[a0 * 32 + g];
                unsigned es = sgnS[a0 * 32 + g];

                as.x += h0.x*e0.x; as.y += h0.y*e0.y;
                as.z += h0.z*e0.z; as.w += h0.w*e0.w;

                float f00 = __uint_as_float((x0.x & 0xffffu) << 16);
                float f01 = __uint_as_float(x0.x & 0xffff0000u);
                float f02 = __uint_as_float((x0.y & 0xffffu) << 16);
                float f03 = __uint_as_float(x0.y & 0xffff0000u);
                al.x += w0.x - fabsf(f00);
                al.y += w0.y - fabsf(f01);
                al.z += w0.z - fabsf(f02);
                al.w += w0.w - fabsf(f03);
                unsigned b0 =  ((~(x0.x >> 15)) & 1u)
                            | (((~(x0.x >> 31)) & 1u) << 1)
                            | (((~(x0.y >> 15)) & 1u) << 2)
                            | (((~(x0.y >> 31)) & 1u) << 3);
                sg ^= es ^ b0;
            }
        }

        *reinterpret_cast<float4*>(&As[r * 128 + g * 4]) = as;

        float4 hp = make_float4(0.f, 0.f, 0.f, 0.f);
        if (n < NN) {
            float dc = (float)deg;
            hp.x = __expf(al.x + dc); if (sg & 1u) hp.x = -hp.x;
            hp.y = __expf(al.y + dc); if (sg & 2u) hp.y = -hp.y;
            hp.z = __expf(al.z + dc); if (sg & 4u) hp.z = -hp.z;
            hp.w = __expf(al.w + dc); if (sg & 8u) hp.w = -hp.w;
        }
        uint2 H, L; split4(hp, H, L);
        *reinterpret_cast<uint2*>(&Ah[r * LDA + g * 4]) = H;
        *reinterpret_cast<uint2*>(&Al[r * LDA + g * 4]) = L;
    }
    __syncthreads();

    // load v tiles into B region (overwrites tables)
    {
        const uint4* s0 = (const uint4*)g_vh;
        const uint4* s1 = (const uint4*)g_vl;
        uint4* d0 = (uint4*)(smem + BH_OFF);
        uint4* d1 = (uint4*)(smem + BL_OFF);
#pragma unroll
        for (int i = 0; i < 2; i++) {
            int idx = tid + i * 1024;
            int row = idx >> 4, col = idx & 15;
            d0[row * 17 + col] = s0[idx];
            d1[row * 17 + col] = s1[idx];
        }
    }
    __syncthreads();

    // Phase 2: MMA 128x128, 32 warps (4 x 8 of 32x16 tiles)
    const int warp_m = wid & 3, warp_n = wid >> 2;
    const uint32_t sbase = smem_to_u32(smem);
    const int nl0 = warp_n * 16;

    float c[2][2][4];
#pragma unroll
    for (int i = 0; i < 2; i++)
#pragma unroll
        for (int j = 0; j < 2; j++)
#pragma unroll
            for (int q = 0; q < 4; q++) c[i][j][q] = 0.f;

#pragma unroll 1
    for (int p = 0; p < 3; p++) {
        uint32_t Abase = sbase + ((p == 2) ? AL_OFF : AH_OFF);
        uint32_t Bbase = sbase + ((p == 1) ? BL_OFF : BH_OFF);
#pragma unroll
        for (int ks = 0; ks < 8; ks++) {
            int k0 = ks * 16;
            uint32_t a[2][4];
#pragma unroll
            for (int i = 0; i < 2; i++) {
                int row = warp_m * 32 + i * 16 + (lane & 15);
                ldsm4(a[i][0], a[i][1], a[i][2], a[i][3],
                      Abase + (uint32_t)(row * LDA + k0 + ((lane >> 4) << 3)) * 2);
            }
            uint32_t b[2][2];
            {
                int o = nl0 + (lane & 7) + ((lane >> 4) << 3);
                uint32_t r0, r1, r2, r3;
                ldsm4(r0, r1, r2, r3,
                      Bbase + (uint32_t)(o * LDA + k0 + (((lane >> 3) & 1) << 3)) * 2);
                b[0][0] = r0; b[0][1] = r1;
                b[1][0] = r2; b[1][1] = r3;
            }
#pragma unroll
            for (int i = 0; i < 2; i++)
#pragma unroll
                for (int j = 0; j < 2; j++)
                    mma_bf16(c[i][j], a[i], b[j]);
        }
    }

    // epilogue: out = (As + C) * rin
#pragma unroll
    for (int i = 0; i < 2; i++) {
        int r0 = warp_m * 32 + i * 16 + (lane >> 2);
        int r1 = r0 + 8;
        int n0 = bid * 128 + r0;
        int n1 = n0 + 8;
        float rin0 = (n0 < NN) ? g_rin[n0] : 0.f;
        float rin1 = (n1 < NN) ? g_rin[n1] : 0.f;
#pragma unroll
        for (int j = 0; j < 2; j++) {
            int col = nl0 + j * 8 + (lane & 3) * 2;
            if (n0 < NN) {
                float2 prev = *reinterpret_cast<float2*>(&As[r0 * 128 + col]);
                *reinterpret_cast<float2*>(&out[(size_t)n0 * F + col]) =
                    make_float2((prev.x + c[i][j][0]) * rin0,
                                (prev.y + c[i][j][1]) * rin0);
            }
            if (n1 < NN) {
                float2 prev = *reinterpret_cast<float2*>(&As[r1 * 128 + col]);
                *reinterpret_cast<float2*>(&out[(size_t)n1 * F + col]) =
                    make_float2((prev.x + c[i][j][2]) * rin1,
                                (prev.y + c[i][j][3]) * rin1);
            }
        }
    }
}

// ---------------- launcher ---------------------------------------------------
#define SMEM_NODE (6 * REG_BYTES)

extern "C" void kernel_launch(void* const* d_in, const int* in_sizes, int n_in,
                              void* d_out, int out_size) {
    const float* feat  = (const float*)d_in[0];
    const int*   src   = (const int*)  d_in[1];
    const int*   dst   = (const int*)  d_in[2];
    const int*   eattr = (const int*)  d_in[3];
    const float* w1    = (const float*)d_in[4];
    const float* w2    = (const float*)d_in[5];
    const float* v     = (const float*)d_in[6];
    const float* bond  = (const float*)d_in[7];
    float* out = (float*)d_out;

    static cudaStream_t s2 = nullptr;
    static cudaEvent_t evFork = nullptr, evJoin = nullptr;
    if (s2 == nullptr) {
        cudaStreamCreateWithFlags(&s2, cudaStreamNonBlocking);
        cudaEventCreateWithFlags(&evFork, cudaEventDisableTiming);
        cudaEventCreateWithFlags(&evJoin, cudaEventDisableTiming);
        cudaFuncSetAttribute(k_node_mma, cudaFuncAttributeMaxDynamicSharedMemorySize, SMEM_NODE);
        cudaFuncSetAttribute(k_fused,    cudaFuncAttributeMaxDynamicSharedMemorySize, SMEM_FUSED);
    }

    void *p_id, *p_od;
    cudaGetSymbolAddress(&p_id, g_indeg_i);
    cudaGetSymbolAddress(&p_od, g_outdeg_i);
    cudaMemsetAsync(p_id, 0, NN * sizeof(int));
    cudaMemsetAsync(p_od, 0, NN * sizeof(int));

    k_count <<<(NE + 255) / 256, 256>>>(src, dst);

    cudaEventRecord(evFork, 0);
    cudaStreamWaitEvent(s2, evFork, 0);

    k_scan1   <<<NB, 256, 0, s2>>>();
    k_scan2   <<<1, 512, 0, s2>>>();
    k_scan3   <<<NB, 256, 0, s2>>>();
    k_scatter <<<(NE + 255) / 256, 256, 0, s2>>>(src, dst, eattr);
    cudaEventRecord(evJoin, s2);

    k_wprep    <<<48, 256>>>(w1, w2, v);
    k_eprep    <<<32, 32>>>(bond);
    k_node_mma <<<NT, 512, SMEM_NODE>>>(feat, w2);

    cudaStreamWaitEvent(0, evJoin, 0);
    k_fused <<<NT, 1024, SMEM_FUSED>>>(bond, out);
}

// round 12
// speedup vs baseline: 1.6176x; 1.2768x over previous
#include <cuda_runtime.h>
#include <cuda_bf16.h>
#include <cstdint>

#define NN 100000
#define NE 800000
#define F  128
#define NT 782              // ceil(NN/128) node tiles
#define NB 391              // ceil(NN/256) scan blocks
#define LDA 136             // smem row stride in bf16 elements
#define REG_BYTES (128 * LDA * 2)   // 34816
#define PKF 192             // pack row stride in floats (512B hs + 256B slhp)

// fused kernel smem layout (bytes)
#define AS_OFF  0                        // 65536: fp32 As
#define AH_OFF  65536                    // 34816: bf16 hp
#define BH_OFF  (AH_OFF + REG_BYTES)     // 34816: bf16 v (hi)
#define EW_OFF  (BH_OFF + REG_BYTES)     // 16384
#define LEW_OFF (EW_OFF + 16384)         // 16384
#define SGN_OFF (LEW_OFF + 16384)        // 4096
#define CNT_OFF (SGN_OFF + 4096)
#define SMEM_FUSED (CNT_OFF + 16)        // 172048

// ---------------- scratch ----------------------------------------------------
__device__ int      g_indeg_i [NN];
__device__ int      g_outdeg_i[NN];
__device__ int      g_rowstart[NN];
__device__ int      g_cursor  [NN];
__device__ float    g_rin     [NN];
__device__ int      g_blksum  [512];
__device__ unsigned g_csr     [NE];
__device__ float    g_pack [(size_t)NN * PKF];   // per node: 128 f32 hs | 128 bf16 slhp
__device__ float    g_lew  [32 * F];
__device__ unsigned g_lewsgn[32 * 32];
__device__ __nv_bfloat16 g_w1h[F * F], g_w1l[F * F];
__device__ __nv_bfloat16 g_w2h[F * F], g_w2l[F * F];
__device__ __nv_bfloat16 g_vh [F * F], g_vl [F * F];

// ---------------- helpers ----------------------------------------------------
__device__ __forceinline__ uint32_t smem_to_u32(const void* p) {
    uint32_t a;
    asm("{ .reg .u64 t; cvta.to.shared.u64 t, %1; cvt.u32.u64 %0, t; }" : "=r"(a) : "l"(p));
    return a;
}

__device__ __forceinline__ void ldsm4(uint32_t& r0, uint32_t& r1, uint32_t& r2, uint32_t& r3,
                                      uint32_t addr) {
    asm volatile("ldmatrix.sync.aligned.m8n8.x4.shared.b16 {%0,%1,%2,%3}, [%4];"
                 : "=r"(r0), "=r"(r1), "=r"(r2), "=r"(r3) : "r"(addr));
}

__device__ __forceinline__ void mma_bf16(float* c, const uint32_t* a, const uint32_t* b) {
    asm volatile("mma.sync.aligned.m16n8k16.row.col.f32.bf16.bf16.f32 "
                 "{%0,%1,%2,%3}, {%4,%5,%6,%7}, {%8,%9}, {%0,%1,%2,%3};"
                 : "+f"(c[0]), "+f"(c[1]), "+f"(c[2]), "+f"(c[3])
                 : "r"(a[0]), "r"(a[1]), "r"(a[2]), "r"(a[3]), "r"(b[0]), "r"(b[1]));
}

__device__ __forceinline__ void split4(float4 x, uint2& H, uint2& L) {
    float xs[4] = {x.x, x.y, x.z, x.w};
    unsigned short h[4], l[4];
#pragma unroll
    for (int j = 0; j < 4; j++) {
        __nv_bfloat16 bh = __float2bfloat16(xs[j]);
        float r = xs[j] - __bfloat162float(bh);
        __nv_bfloat16 bl = __float2bfloat16(r);
        h[j] = __bfloat16_as_ushort(bh);
        l[j] = __bfloat16_as_ushort(bl);
    }
    H = make_uint2((uint32_t)h[0] | ((uint32_t)h[1] << 16),
                   (uint32_t)h[2] | ((uint32_t)h[3] << 16));
    L = make_uint2((uint32_t)l[0] | ((uint32_t)l[1] << 16),
                   (uint32_t)l[2] | ((uint32_t)l[3] << 16));
}

// ---------------- CSR build --------------------------------------------------
__global__ void k_count(const int* __restrict__ src, const int* __restrict__ dst) {
    int e = blockIdx.x * blockDim.x + threadIdx.x;
    if (e < NE) {
        atomicAdd(&g_indeg_i [dst[e]], 1);
        atomicAdd(&g_outdeg_i[src[e]], 1);
    }
}

__global__ void k_scan1() {
    __shared__ int swarp[8];
    int t = threadIdx.x, b = blockIdx.x;
    int i = b * 256 + t;
    int v = (i < NN) ? g_indeg_i[i] : 0;
    int x = v;
    int lane = t & 31, w = t >> 5;
#pragma unroll
    for (int o = 1; o < 32; o <<= 1) {
        int y = __shfl_up_sync(0xffffffffu, x, o);
        if (lane >= o) x += y;
    }
    if (lane == 31) swarp[w] = x;
    __syncthreads();
    if (w == 0) {
        int s = (lane < 8) ? swarp[lane] : 0;
#pragma unroll
        for (int o = 1; o < 8; o <<= 1) {
            int y = __shfl_up_sync(0xffffffffu, s, o);
            if (lane >= o) s += y;
        }
        if (lane < 8) swarp[lane] = s;
    }
    __syncthreads();
    int off = (w > 0) ? swarp[w - 1] : 0;
    if (i < NN) g_rowstart[i] = x - v + off;
    if (t == 255) g_blksum[b] = x + off;
}

__global__ void k_scan2() {
    __shared__ int swarp[16];
    int t = threadIdx.x;
    int v = (t < NB) ? g_blksum[t] : 0;
    int x = v;
    int lane = t & 31, w = t >> 5;
#pragma unroll
    for (int o = 1; o < 32; o <<= 1) {
        int y = __shfl_up_sync(0xffffffffu, x, o);
        if (lane >= o) x += y;
    }
    if (lane == 31) swarp[w] = x;
    __syncthreads();
    if (w == 0) {
        int s = (lane < 16) ? swarp[lane] : 0;
#pragma unroll
        for (int o = 1; o < 16; o <<= 1) {
            int y = __shfl_up_sync(0xffffffffu, s, o);
            if (lane >= o) s += y;
        }
        if (lane < 16) swarp[lane] = s;
    }
    __syncthreads();
    int off = (w > 0) ? swarp[w - 1] : 0;
    if (t < NB) g_blksum[t] = x - v + off;
}

__global__ void k_scan3() {
    int i = blockIdx.x * 256 + threadIdx.x;
    if (i < NN) {
        int r = g_rowstart[i] + g_blksum[blockIdx.x];
        g_rowstart[i] = r;
        g_cursor[i]   = r;
        g_rin[i]      = rsqrtf(fmaxf((float)g_indeg_i[i], 1.0f));
    }
}

__global__ void k_scatter(const int* __restrict__ src, const int* __restrict__ dst,
                          const int* __restrict__ eattr) {
    int e = blockIdx.x * blockDim.x + threadIdx.x;
    if (e < NE) {
        int d = dst[e];
        int pos = atomicAdd(&g_cursor[d], 1);
        g_csr[pos] = (unsigned)src[e] | ((unsigned)eattr[e] << 17);
    }
}

// ---------------- weights -> bf16 hi/lo B^T images --------------------------
__global__ void k_wprep(const float* __restrict__ w1, const float* __restrict__ w2,
                        const float* __restrict__ v) {
    int idx = blockIdx.x * 256 + threadIdx.x;
    if (idx >= 12288) return;
    int mat = idx >> 12;
    int rem = idx & 4095;
    int o  = rem >> 5;
    int k0 = (rem & 31) * 4;
    const float* src = (mat == 0) ? w1 : (mat == 1) ? w2 : v;
    __nv_bfloat16* hi = (mat == 0) ? g_w1h : (mat == 1) ? g_w2h : g_vh;
    __nv_bfloat16* lo = (mat == 0) ? g_w1l : (mat == 1) ? g_w2l : g_vl;
    float4 x;
    x.x = src[(size_t)(k0 + 0) * F + o];
    x.y = src[(size_t)(k0 + 1) * F + o];
    x.z = src[(size_t)(k0 + 2) * F + o];
    x.w = src[(size_t)(k0 + 3) * F + o];
    uint2 H, L; split4(x, H, L);
    *reinterpret_cast<uint2*>(&hi[o * F + k0]) = H;
    *reinterpret_cast<uint2*>(&lo[o * F + k0]) = L;
}

// ---------------- bond -> log|ew| + sign nibbles ----------------------------
__global__ void k_eprep(const float* __restrict__ bond) {
    int t = blockIdx.x;
    int g = threadIdx.x;
    float4 e = *reinterpret_cast<const float4*>(&bond[t * F + g * 4]);
    float4 le;
    le.x = __logf(fabsf(e.x));
    le.y = __logf(fabsf(e.y));
    le.z = __logf(fabsf(e.z));
    le.w = __logf(fabsf(e.w));
    *reinterpret_cast<float4*>(&g_lew[t * F + g * 4]) = le;
    unsigned sgn =  (__float_as_uint(e.x) >> 31)
                 | ((__float_as_uint(e.y) >> 31) << 1)
                 | ((__float_as_uint(e.z) >> 31) << 2)
                 | ((__float_as_uint(e.w) >> 31) << 3);
    g_lewsgn[t * 32 + g] = sgn;
}

// ---------------- fused dual node GEMM via mma.sync (512 threads) -----------
// w1 half: 3-pass bf16 split (feeds output). w2 half: 1-pass (feeds log path).
// smem: Ah | Al | B0=w1h | B1=w1l | B2=w2h  (5 regions)
__global__ __launch_bounds__(512, 1) void k_node_mma(const float* __restrict__ feat,
                                                     const float* __restrict__ w2full) {
    extern __shared__ __align__(16) unsigned char smem[];
    __nv_bfloat16* Ah = (__nv_bfloat16*)smem;
    __nv_bfloat16* Al = Ah + 128 * LDA;
    __nv_bfloat16* Bw[3];
    Bw[0] = Al    + 128 * LDA;
    Bw[1] = Bw[0] + 128 * LDA;
    Bw[2] = Bw[1] + 128 * LDA;

    const int tid = threadIdx.x, lane = tid & 31, wid = tid >> 5;
    const int bid = blockIdx.x;

    {
        int r = tid >> 2, hf = tid & 3;
        int n = bid * 128 + r;
        float s = 0.0f;
        if (n < NN) s = rsqrtf(fmaxf((float)g_outdeg_i[n], 1.0f));
#pragma unroll
        for (int q = 0; q < 8; q++) {
            int k0 = hf * 32 + q * 4;
            float4 x = make_float4(0.f, 0.f, 0.f, 0.f);
            if (n < NN) {
                x = *reinterpret_cast<const float4*>(&feat[(size_t)n * F + k0]);
                x.x *= s; x.y *= s; x.z *= s; x.w *= s;
            }
            uint2 H, L; split4(x, H, L);
            *reinterpret_cast<uint2*>(&Ah[r * LDA + k0]) = H;
            *reinterpret_cast<uint2*>(&Al[r * LDA + k0]) = L;
        }
    }
    {
        const uint4* s0 = (const uint4*)g_w1h;
        const uint4* s1 = (const uint4*)g_w1l;
        const uint4* s2 = (const uint4*)g_w2h;
#pragma unroll
        for (int i = 0; i < 4; i++) {
            int idx = tid + i * 512;
            int row = idx >> 4, col = idx & 15;
            ((uint4*)Bw[0])[row * 17 + col] = s0[idx];
            ((uint4*)Bw[1])[row * 17 + col] = s1[idx];
            ((uint4*)Bw[2])[row * 17 + col] = s2[idx];
        }
    }
    __syncthreads();

    const int warp_m = wid & 1, warp_n = wid >> 1;    // 2 x 8, warp tile 64x32
    const uint32_t sbase = smem_to_u32(smem);
    const uint32_t aAh = sbase, aAl = sbase + REG_BYTES;
    const int nl0 = (warp_n & 3) * 32;

    float c[4][4][4];
#pragma unroll
    for (int i = 0; i < 4; i++)
#pragma unroll
        for (int j = 0; j < 4; j++)
#pragma unroll
            for (int q = 0; q < 4; q++) c[i][j][q] = 0.f;

    const int npass = (warp_n < 4) ? 3 : 1;
#pragma unroll 1
    for (int p = 0; p < npass; p++) {
        uint32_t Abase = (p == 2) ? aAl : aAh;
        int bsel = (warp_n < 4) ? ((p == 1) ? 1 : 0) : 2;
        uint32_t Bbase = sbase + (uint32_t)(2 + bsel) * REG_BYTES;
#pragma unroll
        for (int ks = 0; ks < 8; ks++) {
            int k0 = ks * 16;
            uint32_t a[4][4];
#pragma unroll
            for (int i = 0; i < 4; i++) {
                int row = warp_m * 64 + i * 16 + (lane & 15);
                ldsm4(a[i][0], a[i][1], a[i][2], a[i][3],
                      Abase + (uint32_t)(row * LDA + k0 + ((lane >> 4) << 3)) * 2);
            }
            uint32_t b[4][2];
#pragma unroll
            for (int jj = 0; jj < 2; jj++) {
                int o = nl0 + jj * 16 + (lane & 7) + ((lane >> 4) << 3);
                uint32_t r0, r1, r2, r3;
                ldsm4(r0, r1, r2, r3,
                      Bbase + (uint32_t)(o * LDA + k0 + (((lane >> 3) & 1) << 3)) * 2);
                b[jj * 2][0] = r0; b[jj * 2][1] = r1;
                b[jj * 2 + 1][0] = r2; b[jj * 2 + 1][1] = r3;
            }
#pragma unroll
            for (int i = 0; i < 4; i++)
#pragma unroll
                for (int j = 0; j < 4; j++)
                    mma_bf16(c[i][j], a[i], b[j]);
        }
    }

    const int colbase = warp_n * 32;
    unsigned* packu = (unsigned*)g_pack;
#pragma unroll
    for (int i = 0; i < 4; i++) {
        int r0 = warp_m * 64 + i * 16 + (lane >> 2);
        int n0 = bid * 128 + r0;
        int n1 = n0 + 8;
#pragma unroll
        for (int j = 0; j < 4; j++) {
            int col = colbase + j * 8 + (lane & 3) * 2;
            if (col < 128) {
                if (n0 < NN)
                    *reinterpret_cast<float2*>(&g_pack[(size_t)n0 * PKF + col]) =
                        make_float2(c[i][j][0], c[i][j][1]);
                if (n1 < NN)
                    *reinterpret_cast<float2*>(&g_pack[(size_t)n1 * PKF + col]) =
                        make_float2(c[i][j][2], c[i][j][3]);
            } else {
                int c2 = col - 128;
                float2 bias = *reinterpret_cast<const float2*>(&w2full[(size_t)128 * F + c2]);
                if (n0 < NN) {
                    float t0 = tanhf(c[i][j][0] + bias.x);
                    float t1 = tanhf(c[i][j][1] + bias.y);
                    float l0 = __logf(fabsf(t0)) - 1.0f;
                    float l1 = __logf(fabsf(t1)) - 1.0f;
                    float s0 = (t0 < 0.f) ? -l0 : l0;
                    float s1 = (t1 < 0.f) ? -l1 : l1;
                    unsigned pk = (unsigned)__bfloat16_as_ushort(__float2bfloat16(s0))
                                | ((unsigned)__bfloat16_as_ushort(__float2bfloat16(s1)) << 16);
                    packu[(size_t)n0 * PKF + 128 + (c2 >> 1)] = pk;
                }
                if (n1 < NN) {
                    float t0 = tanhf(c[i][j][2] + bias.x);
                    float t1 = tanhf(c[i][j][3] + bias.y);
                    float l0 = __logf(fabsf(t0)) - 1.0f;
                    float l1 = __logf(fabsf(t1)) - 1.0f;
                    float s0 = (t0 < 0.f) ? -l0 : l0;
                    float s1 = (t1 < 0.f) ? -l1 : l1;
                    unsigned pk = (unsigned)__bfloat16_as_ushort(__float2bfloat16(s0))
                                | ((unsigned)__bfloat16_as_ushort(__float2bfloat16(s1)) << 16);
                    packu[(size_t)n1 * PKF + 128 + (c2 >> 1)] = pk;
                }
            }
        }
    }
}

// ---------------- fused gather + final GEMM (1024 threads) -------------------
// Phase 1: dynamic-row gather -> As (fp32 smem) + hp (bf16 smem, single image)
// Phase 2: single-pass MMA hp_bf16 @ v_hi; epilogue out = (As + C) * rin
__global__ __launch_bounds__(1024, 1) void k_fused(const float* __restrict__ bond,
                                                   float* __restrict__ out) {
    extern __shared__ __align__(16) unsigned char smem[];
    float*        As  = (float*)(smem + AS_OFF);
    __nv_bfloat16* Ah = (__nv_bfloat16*)(smem + AH_OFF);
    float*        ewS  = (float*)(smem + EW_OFF);
    float*        lewS = (float*)(smem + LEW_OFF);
    unsigned*     sgnS = (unsigned*)(smem + SGN_OFF);
    int*          cnt  = (int*)(smem + CNT_OFF);

    const int tid = threadIdx.x, lane = tid & 31, wid = tid >> 5;
    const int bid = blockIdx.x;
    const int g = lane;

    // stage tables + v(hi) tile; init row counter
    {
        const uint4* s0 = (const uint4*)g_vh;
        uint4* d0 = (uint4*)(smem + BH_OFF);
#pragma unroll
        for (int i = 0; i < 2; i++) {
            int idx = tid + i * 1024;
            int row = idx >> 4, col = idx & 15;
            d0[row * 17 + col] = s0[idx];
        }
#pragma unroll
        for (int i = 0; i < 4; i++) {
            int idx = tid + i * 1024;
            ewS[idx]  = bond[idx];
            lewS[idx] = g_lew[idx];
        }
        if (tid < 1024) sgnS[tid] = g_lewsgn[tid];
        if (tid == 0) *cnt = 0;
    }
    __syncthreads();

    const float4* pk4 = (const float4*)g_pack;   // 48 float4 per row
    const uint2*  pk2 = (const uint2*)g_pack;    // 96 uint2 per row; slhp at +64
    const float4* ew4 = (const float4*)ewS;
    const float4* lw4 = (const float4*)lewS;

    // Phase 1: gather, dynamic row assignment
    for (;;) {
        int r;
        if (lane == 0) r = atomicAdd(cnt, 1);
        r = __shfl_sync(0xffffffffu, r, 0);
        if (r >= 128) break;
        int n = bid * 128 + r;

        float4 as = make_float4(0.f, 0.f, 0.f, 0.f);
        float4 al = make_float4(0.f, 0.f, 0.f, 0.f);
        unsigned sg = 0;
        int deg = 0;

        if (n < NN) {
            int base = g_rowstart[n];
            deg = g_indeg_i[n];
            int i = 0;
            for (; i + 2 <= deg; i += 2) {
                unsigned c0 = __ldg(&g_csr[base + i]);
                unsigned c1 = __ldg(&g_csr[base + i + 1]);
                int s0 = c0 & 0x1FFFF, a0 = c0 >> 17;
                int s1 = c1 & 0x1FFFF, a1 = c1 >> 17;
                float4 h0 = __ldg(pk4 + (size_t)s0 * 48 + g);
                float4 h1 = __ldg(pk4 + (size_t)s1 * 48 + g);
                uint2  x0 = __ldg(pk2 + (size_t)s0 * 96 + 64 + g);
                uint2  x1 = __ldg(pk2 + (size_t)s1 * 96 + 64 + g);
                float4 e0 = ew4[a0 * 32 + g];
                float4 e1 = ew4[a1 * 32 + g];
                float4 w0 = lw4[a0 * 32 + g];
                float4 w1 = lw4[a1 * 32 + g];
                unsigned es = sgnS[a0 * 32 + g] ^ sgnS[a1 * 32 + g];

                as.x += h0.x*e0.x + h1.x*e1.x;
                as.y += h0.y*e0.y + h1.y*e1.y;
                as.z += h0.z*e0.z + h1.z*e1.z;
                as.w += h0.w*e0.w + h1.w*e1.w;

                float f00 = __uint_as_float((x0.x & 0xffffu) << 16);
                float f01 = __uint_as_float(x0.x & 0xffff0000u);
                float f02 = __uint_as_float((x0.y & 0xffffu) << 16);
                float f03 = __uint_as_float(x0.y & 0xffff0000u);
                float f10 = __uint_as_float((x1.x & 0xffffu) << 16);
                float f11 = __uint_as_float(x1.x & 0xffff0000u);
                float f12 = __uint_as_float((x1.y & 0xffffu) << 16);
                float f13 = __uint_as_float(x1.y & 0xffff0000u);

                al.x += (w0.x - fabsf(f00)) + (w1.x - fabsf(f10));
                al.y += (w0.y - fabsf(f01)) + (w1.y - fabsf(f11));
                al.z += (w0.z - fabsf(f02)) + (w1.z - fabsf(f12));
                al.w += (w0.w - fabsf(f03)) + (w1.w - fabsf(f13));

                unsigned b0 =  ((~(x0.x >> 15)) & 1u)
                            | (((~(x0.x >> 31)) & 1u) << 1)
                            | (((~(x0.y >> 15)) & 1u) << 2)
                            | (((~(x0.y >> 31)) & 1u) << 3);
                unsigned b1 =  ((~(x1.x >> 15)) & 1u)
                            | (((~(x1.x >> 31)) & 1u) << 1)
                            | (((~(x1.y >> 15)) & 1u) << 2)
                            | (((~(x1.y >> 31)) & 1u) << 3);
                sg ^= es ^ b0 ^ b1;
            }
            if (i < deg) {
                unsigned c0 = __ldg(&g_csr[base + i]);
                int s0 = c0 & 0x1FFFF, a0 = c0 >> 17;
                float4 h0 = __ldg(pk4 + (size_t)s0 * 48 + g);
                uint2  x0 = __ldg(pk2 + (size_t)s0 * 96 + 64 + g);
                float4 e0 = ew4[a0 * 32 + g];
                float4 w0 = lw4[a0 * 32 + g];
                unsigned es = sgnS[a0 * 32 + g];

                as.x += h0.x*e0.x; as.y += h0.y*e0.y;
                as.z += h0.z*e0.z; as.w += h0.w*e0.w;

                float f00 = __uint_as_float((x0.x & 0xffffu) << 16);
                float f01 = __uint_as_float(x0.x & 0xffff0000u);
                float f02 = __uint_as_float((x0.y & 0xffffu) << 16);
                float f03 = __uint_as_float(x0.y & 0xffff0000u);
                al.x += w0.x - fabsf(f00);
                al.y += w0.y - fabsf(f01);
                al.z += w0.z - fabsf(f02);
                al.w += w0.w - fabsf(f03);
                unsigned b0 =  ((~(x0.x >> 15)) & 1u)
                            | (((~(x0.x >> 31)) & 1u) << 1)
                            | (((~(x0.y >> 15)) & 1u) << 2)
                            | (((~(x0.y >> 31)) & 1u) << 3);
                sg ^= es ^ b0;
            }
        }

        *reinterpret_cast<float4*>(&As[r * 128 + g * 4]) = as;

        // hp = sign * exp(al + deg) -> bf16 (single image)
        float hx = 0.f, hy = 0.f, hz = 0.f, hw = 0.f;
        if (n < NN) {
            float dc = (float)deg;
            hx = __expf(al.x + dc); if (sg & 1u) hx = -hx;
            hy = __expf(al.y + dc); if (sg & 2u) hy = -hy;
            hz = __expf(al.z + dc); if (sg & 4u) hz = -hz;
            hw = __expf(al.w + dc); if (sg & 8u) hw = -hw;
        }
        unsigned p0 = (unsigned)__bfloat16_as_ushort(__float2bfloat16(hx))
                    | ((unsigned)__bfloat16_as_ushort(__float2bfloat16(hy)) << 16);
        unsigned p1 = (unsigned)__bfloat16_as_ushort(__float2bfloat16(hz))
                    | ((unsigned)__bfloat16_as_ushort(__float2bfloat16(hw)) << 16);
        *reinterpret_cast<uint2*>(&Ah[r * LDA + g * 4]) = make_uint2(p0, p1);
    }
    __syncthreads();

    // Phase 2: single-pass MMA 128x128, 32 warps (4 x 8 of 32x16 tiles)
    const int warp_m = wid & 3, warp_n = wid >> 2;
    const uint32_t sbase = smem_to_u32(smem);
    const int nl0 = warp_n * 16;

    float c[2][2][4];
#pragma unroll
    for (int i = 0; i < 2; i++)
#pragma unroll
        for (int j = 0; j < 2; j++)
#pragma unroll
            for (int q = 0; q < 4; q++) c[i][j][q] = 0.f;

    {
        uint32_t Abase = sbase + AH_OFF;
        uint32_t Bbase = sbase + BH_OFF;
#pragma unroll
        for (int ks = 0; ks < 8; ks++) {
            int k0 = ks * 16;
            uint32_t a[2][4];
#pragma unroll
            for (int i = 0; i < 2; i++) {
                int row = warp_m * 32 + i * 16 + (lane & 15);
                ldsm4(a[i][0], a[i][1], a[i][2], a[i][3],
                      Abase + (uint32_t)(row * LDA + k0 + ((lane >> 4) << 3)) * 2);
            }
            uint32_t b[2][2];
            {
                int o = nl0 + (lane & 7) + ((lane >> 4) << 3);
                uint32_t r0, r1, r2, r3;
                ldsm4(r0, r1, r2, r3,
                      Bbase + (uint32_t)(o * LDA + k0 + (((lane >> 3) & 1) << 3)) * 2);
                b[0][0] = r0; b[0][1] = r1;
                b[1][0] = r2; b[1][1] = r3;
            }
#pragma unroll
            for (int i = 0; i < 2; i++)
#pragma unroll
                for (int j = 0; j < 2; j++)
                    mma_bf16(c[i][j], a[i], b[j]);
        }
    }

    // epilogue: out = (As + C) * rin
#pragma unroll
    for (int i = 0; i < 2; i++) {
        int r0 = warp_m * 32 + i * 16 + (lane >> 2);
        int r1 = r0 + 8;
        int n0 = bid * 128 + r0;
        int n1 = n0 + 8;
        float rin0 = (n0 < NN) ? g_rin[n0] : 0.f;
        float rin1 = (n1 < NN) ? g_rin[n1] : 0.f;
#pragma unroll
        for (int j = 0; j < 2; j++) {
            int col = nl0 + j * 8 + (lane & 3) * 2;
            if (n0 < NN) {
                float2 prev = *reinterpret_cast<float2*>(&As[r0 * 128 + col]);
                *reinterpret_cast<float2*>(&out[(size_t)n0 * F + col]) =
                    make_float2((prev.x + c[i][j][0]) * rin0,
                                (prev.y + c[i][j][1]) * rin0);
            }
            if (n1 < NN) {
                float2 prev = *reinterpret_cast<float2*>(&As[r1 * 128 + col]);
                *reinterpret_cast<float2*>(&out[(size_t)n1 * F + col]) =
                    make_float2((prev.x + c[i][j][2]) * rin1,
                                (prev.y + c[i][j][3]) * rin1);
            }
        }
    }
}

// ---------------- launcher ---------------------------------------------------
#define SMEM_NODE (5 * REG_BYTES)

extern "C" void kernel_launch(void* const* d_in, const int* in_sizes, int n_in,
                              void* d_out, int out_size) {
    const float* feat  = (const float*)d_in[0];
    const int*   src   = (const int*)  d_in[1];
    const int*   dst   = (const int*)  d_in[2];
    const int*   eattr = (const int*)  d_in[3];
    const float* w1    = (const float*)d_in[4];
    const float* w2    = (const float*)d_in[5];
    const float* v     = (const float*)d_in[6];
    const float* bond  = (const float*)d_in[7];
    float* out = (float*)d_out;

    static cudaStream_t s2 = nullptr;
    static cudaEvent_t evFork = nullptr, evJoin = nullptr;
    if (s2 == nullptr) {
        cudaStreamCreateWithFlags(&s2, cudaStreamNonBlocking);
        cudaEventCreateWithFlags(&evFork, cudaEventDisableTiming);
        cudaEventCreateWithFlags(&evJoin, cudaEventDisableTiming);
        cudaFuncSetAttribute(k_node_mma, cudaFuncAttributeMaxDynamicSharedMemorySize, SMEM_NODE);
        cudaFuncSetAttribute(k_fused,    cudaFuncAttributeMaxDynamicSharedMemorySize, SMEM_FUSED);
    }

    void *p_id, *p_od;
    cudaGetSymbolAddress(&p_id, g_indeg_i);
    cudaGetSymbolAddress(&p_od, g_outdeg_i);
    cudaMemsetAsync(p_id, 0, NN * sizeof(int));
    cudaMemsetAsync(p_od, 0, NN * sizeof(int));

    k_count <<<(NE + 255) / 256, 256>>>(src, dst);

    cudaEventRecord(evFork, 0);
    cudaStreamWaitEvent(s2, evFork, 0);

    k_scan1   <<<NB, 256, 0, s2>>>();
    k_scan2   <<<1, 512, 0, s2>>>();
    k_scan3   <<<NB, 256, 0, s2>>>();
    k_scatter <<<(NE + 255) / 256, 256, 0, s2>>>(src, dst, eattr);
    cudaEventRecord(evJoin, s2);

    k_wprep    <<<48, 256>>>(w1, w2, v);
    k_eprep    <<<32, 32>>>(bond);
    k_node_mma <<<NT, 512, SMEM_NODE>>>(feat, w2);

    cudaStreamWaitEvent(0, evJoin, 0);
    k_fused <<<NT, 1024, SMEM_FUSED>>>(bond, out);
}